// round 7
// baseline (speedup 1.0000x reference)
#include <cuda_runtime.h>
#include <cuda_bf16.h>
#include <cuda_fp16.h>
#include <cstdint>

#define N_NODES 10000
#define EDGES   160000
#define EMBED   128
#define HEADS   16
#define HC      2048
#define NEG_SLOPE 0.2f
#define M_SENT  (-1e30f)
#define MT      128
#define MTILES  79
#define MPAD    (MTILES * MT)      // 10112
#define KSPLIT  4

// ===================== device scratch =======================================
__device__ int   g_is64;
__device__ int   g_src[EDGES];
__device__ int   g_dst[EDGES];
__device__ int   g_deg[N_NODES];
__device__ int   g_rowptr[N_NODES + 1];
__device__ int   g_cursor[N_NODES];
__device__ int   g_col[EDGES + N_NODES];

__device__ float g_waS[HEADS * EMBED];                   // W1_h @ a_src1_h
__device__ float g_waD[HEADS * EMBED];
__device__ __nv_bfloat16 g_w1t_hi[(size_t)HC * EMBED];   // [n=2048][k=128]
__device__ __nv_bfloat16 g_w1t_lo[(size_t)HC * EMBED];
__device__ __nv_bfloat16 g_w2t_hi[(size_t)EMBED * HC];   // [n=128][k=2048]
__device__ __nv_bfloat16 g_w2t_lo[(size_t)EMBED * HC];
__device__ float g_als1[MPAD * HEADS];
__device__ float g_ald1[MPAD * HEADS];
__device__ __nv_bfloat16 g_axhi[(size_t)MPAD * HC];      // aggregated x per head
__device__ __nv_bfloat16 g_axlo[(size_t)MPAD * HC];
__device__ __nv_bfloat16 g_x2hi[(size_t)MPAD * HC];
__device__ __nv_bfloat16 g_x2lo[(size_t)MPAD * HC];
__device__ float g_h2p[(size_t)KSPLIT * MPAD * EMBED];
__device__ __half g_h2[(size_t)MPAD * EMBED];
__device__ float g_als2[MPAD];
__device__ float g_ald2[MPAD];

// ===================== prep =================================================
template <int R, int C>
__device__ void transpose_cv(const float* __restrict__ src,
                             __nv_bfloat16* __restrict__ dhi,
                             __nv_bfloat16* __restrict__ dlo, int bx, int by) {
    __shared__ float tile[32][33];
    int tx = threadIdx.x & 31, ty0 = threadIdx.x >> 5;
    #pragma unroll
    for (int j = 0; j < 4; j++) {
        int r = by * 32 + ty0 + j * 8, c = bx * 32 + tx;
        tile[ty0 + j * 8][tx] = src[(size_t)r * C + c];
    }
    __syncthreads();
    #pragma unroll
    for (int j = 0; j < 4; j++) {
        int rd = bx * 32 + ty0 + j * 8;
        int cd = by * 32 + tx;
        float v = tile[tx][ty0 + j * 8];
        __nv_bfloat16 h = __float2bfloat16(v);
        dhi[(size_t)rd * R + cd] = h;
        dlo[(size_t)rd * R + cd] = __float2bfloat16(v - __bfloat162float(h));
    }
}

#define NB_WA  16
#define NB_W1  256
#define NB_W2  256
#define NB_DEG 40

__global__ void prep_kernel(const float* __restrict__ W1,
                            const float* __restrict__ W2,
                            const float* __restrict__ as1,
                            const float* __restrict__ ad1,
                            const void* __restrict__ ei) {
    int b = blockIdx.x, t = threadIdx.x;
    if (b < NB_WA) {   // waS/waD for head b
        __shared__ float sa[EMBED], sd[EMBED];
        int h = b;
        if (t < 128) { sa[t] = as1[h * EMBED + t]; sd[t] = ad1[h * EMBED + t]; }
        __syncthreads();
        if (t < 128) {
            float ss = 0.f, ssd = 0.f;
            const float* wrow = W1 + (size_t)t * HC + h * EMBED;
            #pragma unroll 4
            for (int c = 0; c < EMBED; c++) {
                float w = wrow[c];
                ss += w * sa[c];
                ssd += w * sd[c];
            }
            g_waS[h * EMBED + t] = ss;
            g_waD[h * EMBED + t] = ssd;
        }
        return;
    }
    b -= NB_WA;
    if (b < NB_W1) { transpose_cv<128, 2048>(W1, g_w1t_hi, g_w1t_lo, b & 63, b >> 6); return; }
    b -= NB_W1;
    if (b < NB_W2) { transpose_cv<2048, 128>(W2, g_w2t_hi, g_w2t_lo, b & 3, b >> 2); return; }
    b -= NB_W2;
    if (b < NB_DEG) {
        int idx = b * 256 + t;
        if (idx < N_NODES) g_deg[idx] = 1;
        return;
    }
    const long long* p = (const long long*)ei;
    long long v = p[t];
    int ok = (v >= 0 && v < N_NODES);
    int all = __syncthreads_and(ok);
    if (t == 0) g_is64 = all;
}

__global__ void decode_count_kernel(const void* __restrict__ ei, int E) {
    int i = blockIdx.x * blockDim.x + threadIdx.x;
    if (i >= 2 * E) return;
    int vi = g_is64 ? (int)((const long long*)ei)[i] : ((const int*)ei)[i];
    if (i < E) g_src[i] = vi;
    else { g_dst[i - E] = vi; atomicAdd(&g_deg[vi], 1); }
}

__global__ void scan_kernel(int n) {
    __shared__ int wsum[32];
    int tid = threadIdx.x;
    int CH = (n + 1023) / 1024;
    int base = tid * CH;
    int s = 0;
    for (int k = 0; k < CH; k++) { int idx = base + k; if (idx < n) s += g_deg[idx]; }
    int lane = tid & 31, wid = tid >> 5;
    int v = s;
    #pragma unroll
    for (int o = 1; o < 32; o <<= 1) {
        int t2 = __shfl_up_sync(0xffffffffu, v, o);
        if (lane >= o) v += t2;
    }
    if (lane == 31) wsum[wid] = v;
    __syncthreads();
    if (wid == 0) {
        int w = wsum[lane];
        #pragma unroll
        for (int o = 1; o < 32; o <<= 1) {
            int t2 = __shfl_up_sync(0xffffffffu, w, o);
            if (lane >= o) w += t2;
        }
        wsum[lane] = w;
    }
    __syncthreads();
    int excl = v - s + (wid ? wsum[wid - 1] : 0);
    int running = excl;
    for (int k = 0; k < CH; k++) {
        int idx = base + k;
        if (idx < n) {
            g_rowptr[idx] = running;
            g_cursor[idx] = running;
            running += g_deg[idx];
        }
    }
    if (tid == 0) g_rowptr[n] = wsum[31];
}

__global__ void fill_kernel(int E, int n) {
    int i = blockIdx.x * blockDim.x + threadIdx.x;
    if (i < E) {
        int d = g_dst[i];
        int pos = atomicAdd(&g_cursor[d], 1);
        g_col[pos] = g_src[i];
    } else if (i < E + n) {
        int v = i - E;
        int pos = atomicAdd(&g_cursor[v], 1);
        g_col[pos] = v;
    }
}

// ===================== logits for layer 1: x . waS / waD ====================
__global__ void logits1_kernel(const float* __restrict__ x, int n) {
    int node = blockIdx.x * 8 + (threadIdx.x >> 5);
    if (node >= n) return;
    int lane = threadIdx.x & 31;
    float4 xv = ((const float4*)(x + (size_t)node * EMBED))[lane];
    #pragma unroll
    for (int h = 0; h < HEADS; h++) {
        float4 wS = ((const float4*)(g_waS + h * EMBED))[lane];
        float4 wD = ((const float4*)(g_waD + h * EMBED))[lane];
        float ss = xv.x * wS.x + xv.y * wS.y + xv.z * wS.z + xv.w * wS.w;
        float sd = xv.x * wD.x + xv.y * wD.y + xv.z * wD.z + xv.w * wD.w;
        #pragma unroll
        for (int o = 16; o > 0; o >>= 1) {
            ss += __shfl_xor_sync(0xffffffffu, ss, o);
            sd += __shfl_xor_sync(0xffffffffu, sd, o);
        }
        if (lane == 0) {
            g_als1[node * HEADS + h] = ss;
            g_ald1[node * HEADS + h] = sd;
        }
    }
}

// ===================== agg1: aggregate x with per-head softmax ==============
__global__ void agg1_kernel(const float* __restrict__ x) {
    int nno = blockIdx.x;
    int t = threadIdx.x;          // 256 threads
    int h = t >> 4;
    int c0 = (t & 15) * 8;
    int beg = g_rowptr[nno], end = g_rowptr[nno + 1];
    float ad = g_ald1[nno * HEADS + h];
    float m = M_SENT, s = 0.f;
    float a[8];
    #pragma unroll
    for (int i = 0; i < 8; i++) a[i] = 0.f;

    for (int j = beg; j < end; j++) {
        int src = __ldg(&g_col[j]);
        float lg = __ldg(&g_als1[src * HEADS + h]) + ad;
        lg = lg > 0.f ? lg : NEG_SLOPE * lg;
        float4 x0 = __ldg((const float4*)(x + (size_t)src * EMBED + c0));
        float4 x1 = __ldg((const float4*)(x + (size_t)src * EMBED + c0 + 4));
        float hv[8] = {x0.x, x0.y, x0.z, x0.w, x1.x, x1.y, x1.z, x1.w};
        if (lg > m) {
            float sc = (m == M_SENT) ? 0.f : __expf(m - lg);
            s = s * sc + 1.f;
            #pragma unroll
            for (int i = 0; i < 8; i++) a[i] = a[i] * sc + hv[i];
            m = lg;
        } else {
            float p = __expf(lg - m);
            s += p;
            #pragma unroll
            for (int i = 0; i < 8; i++) a[i] += p * hv[i];
        }
    }
    float inv = 1.f / (s + 1e-16f);
    __align__(16) __nv_bfloat16 hb[8], lb[8];
    #pragma unroll
    for (int i = 0; i < 8; i++) {
        float v = a[i] * inv;
        __nv_bfloat16 hi = __float2bfloat16(v);
        hb[i] = hi;
        lb[i] = __float2bfloat16(v - __bfloat162float(hi));
    }
    size_t off = (size_t)nno * HC + h * EMBED + c0;
    *(float4*)(g_axhi + off) = *(float4*)hb;
    *(float4*)(g_axlo + off) = *(float4*)lb;
}

// ===================== mma.sync GEMM machinery ==============================
#define SKW 72
#define CHUNK_B (128 * SKW * 2)

__device__ __forceinline__ void mma16816(float* c, const uint32_t* a, const uint32_t* b) {
    asm volatile("mma.sync.aligned.m16n8k16.row.col.f32.bf16.bf16.f32 "
        "{%0,%1,%2,%3}, {%4,%5,%6,%7}, {%8,%9}, {%0,%1,%2,%3};"
        : "+f"(c[0]), "+f"(c[1]), "+f"(c[2]), "+f"(c[3])
        : "r"(a[0]), "r"(a[1]), "r"(a[2]), "r"(a[3]), "r"(b[0]), "r"(b[1]));
}

__device__ __forceinline__ void fetch_chunk(const __nv_bfloat16* __restrict__ src,
                                            int ld, int row0, int k0,
                                            float4* r, int tid) {
    #pragma unroll
    for (int i = 0; i < 4; i++) {
        int c = tid + i * 256;
        int row = c >> 3;
        int kk = (c & 7) * 8;
        r[i] = *(const float4*)(src + (size_t)(row0 + row) * ld + k0 + kk);
    }
}

__device__ __forceinline__ void stash_chunk(const float4* r,
                                            __nv_bfloat16 (*S)[SKW], int tid) {
    #pragma unroll
    for (int i = 0; i < 4; i++) {
        int c = tid + i * 256;
        int row = c >> 3;
        int kk = (c & 7) * 8;
        *(float4*)&S[row][kk] = r[i];
    }
}

__device__ __forceinline__ void mma_chunk(const __nv_bfloat16 (*As)[SKW],
                                          const __nv_bfloat16 (*Bs)[SKW],
                                          float c[2][8][4],
                                          int warp_m, int warp_n, int lane) {
    int g = lane >> 2, tig = lane & 3;
    #pragma unroll
    for (int ks = 0; ks < 4; ks++) {
        int k0 = ks * 16;
        uint32_t a[2][4], b[8][2];
        #pragma unroll
        for (int mt = 0; mt < 2; mt++) {
            int r = warp_m * 32 + mt * 16 + g;
            a[mt][0] = *(const uint32_t*)&As[r][k0 + tig * 2];
            a[mt][1] = *(const uint32_t*)&As[r + 8][k0 + tig * 2];
            a[mt][2] = *(const uint32_t*)&As[r][k0 + tig * 2 + 8];
            a[mt][3] = *(const uint32_t*)&As[r + 8][k0 + tig * 2 + 8];
        }
        #pragma unroll
        for (int nt = 0; nt < 8; nt++) {
            int n = warp_n * 64 + nt * 8 + g;
            b[nt][0] = *(const uint32_t*)&Bs[n][k0 + tig * 2];
            b[nt][1] = *(const uint32_t*)&Bs[n][k0 + tig * 2 + 8];
        }
        #pragma unroll
        for (int mt = 0; mt < 2; mt++)
            #pragma unroll
            for (int nt = 0; nt < 8; nt++)
                mma16816(c[mt][nt], a[mt], b[nt]);
    }
}

// ===================== expand1: x2 = ELU(aggx @ W1_h + b1) ==================
#define G1_SMEM (4 * CHUNK_B + 128 * 4)

__global__ __launch_bounds__(256) void expand1_kernel(const float* __restrict__ b1) {
    extern __shared__ char dsm[];
    __nv_bfloat16 (*Ab[2])[SKW] = {(__nv_bfloat16(*)[SKW])dsm,
                                   (__nv_bfloat16(*)[SKW])(dsm + 2 * CHUNK_B)};
    __nv_bfloat16 (*Bb[2])[SKW] = {(__nv_bfloat16(*)[SKW])(dsm + CHUNK_B),
                                   (__nv_bfloat16(*)[SKW])(dsm + 3 * CHUNK_B)};
    float* s_b = (float*)(dsm + 4 * CHUNK_B);

    int tid = threadIdx.x;
    int wid = tid >> 5, lane = tid & 31;
    int warp_m = wid & 3, warp_n = wid >> 2;
    int g = lane >> 2, tig = lane & 3;
    int h = blockIdx.x;
    int m0 = blockIdx.y * MT;

    if (tid < 128) s_b[tid] = b1[h * EMBED + tid];

    float c[2][8][4];
    #pragma unroll
    for (int mt = 0; mt < 2; mt++)
        #pragma unroll
        for (int nt = 0; nt < 8; nt++)
            #pragma unroll
            for (int i = 0; i < 4; i++) c[mt][nt][i] = 0.f;

    float4 pa[4], pb[4];
    fetch_chunk(g_axhi, HC, m0, h * EMBED, pa, tid);
    fetch_chunk(g_w1t_hi, EMBED, h * 128, 0, pb, tid);
    #pragma unroll
    for (int it = 0; it < 6; it++) {
        stash_chunk(pa, Ab[it & 1], tid);
        stash_chunk(pb, Bb[it & 1], tid);
        __syncthreads();
        if (it + 1 < 6) {
            int nx = it + 1;
            int p = nx >> 1, kc = (nx & 1) * 64;
            const __nv_bfloat16* Asrc = (p == 2) ? g_axlo : g_axhi;
            const __nv_bfloat16* Bsrc = (p == 1) ? g_w1t_lo : g_w1t_hi;
            fetch_chunk(Asrc, HC, m0, h * EMBED + kc, pa, tid);
            fetch_chunk(Bsrc, EMBED, h * 128, kc, pb, tid);
        }
        mma_chunk(Ab[it & 1], Bb[it & 1], c, warp_m, warp_n, lane);
        __syncthreads();
    }

    // epilogue: bias + ELU + bf16 hi/lo split
    #pragma unroll
    for (int mt = 0; mt < 2; mt++) {
        int r = warp_m * 32 + mt * 16 + g;
        #pragma unroll
        for (int nt = 0; nt < 8; nt++) {
            int col = warp_n * 64 + nt * 8 + tig * 2;
            float* cc = c[mt][nt];
            #pragma unroll
            for (int q = 0; q < 2; q++) {
                float v0 = cc[q * 2 + 0] + s_b[col];
                float v1 = cc[q * 2 + 1] + s_b[col + 1];
                v0 = v0 > 0.f ? v0 : (__expf(v0) - 1.f);
                v1 = v1 > 0.f ? v1 : (__expf(v1) - 1.f);
                __nv_bfloat16 h0 = __float2bfloat16(v0);
                __nv_bfloat16 h1 = __float2bfloat16(v1);
                __nv_bfloat162 hh; hh.x = h0; hh.y = h1;
                __nv_bfloat162 ll;
                ll.x = __float2bfloat16(v0 - __bfloat162float(h0));
                ll.y = __float2bfloat16(v1 - __bfloat162float(h1));
                size_t base = (size_t)(m0 + r + q * 8) * HC + h * EMBED + col;
                *(__nv_bfloat162*)(g_x2hi + base) = hh;
                *(__nv_bfloat162*)(g_x2lo + base) = ll;
            }
        }
    }
}

// ===================== GEMM2: K-split partials ==============================
#define G2_SMEM (4 * CHUNK_B)
#define G2_NIT  24

__global__ __launch_bounds__(256) void gemm2_kernel() {
    extern __shared__ char dsm[];
    __nv_bfloat16 (*Ab[2])[SKW] = {(__nv_bfloat16(*)[SKW])dsm,
                                   (__nv_bfloat16(*)[SKW])(dsm + 2 * CHUNK_B)};
    __nv_bfloat16 (*Bb[2])[SKW] = {(__nv_bfloat16(*)[SKW])(dsm + CHUNK_B),
                                   (__nv_bfloat16(*)[SKW])(dsm + 3 * CHUNK_B)};

    int tid = threadIdx.x;
    int wid = tid >> 5, lane = tid & 31;
    int warp_m = wid & 3, warp_n = wid >> 2;
    int g = lane >> 2, tig = lane & 3;
    int m0 = blockIdx.x * MT;
    int ks = blockIdx.y * 512;

    float c[2][8][4];
    #pragma unroll
    for (int mt = 0; mt < 2; mt++)
        #pragma unroll
        for (int nt = 0; nt < 8; nt++)
            #pragma unroll
            for (int i = 0; i < 4; i++) c[mt][nt][i] = 0.f;

    float4 pa[4], pb[4];
    fetch_chunk(g_x2hi, HC, m0, ks, pa, tid);
    fetch_chunk(g_w2t_hi, HC, 0, ks, pb, tid);
    for (int it = 0; it < G2_NIT; it++) {
        stash_chunk(pa, Ab[it & 1], tid);
        stash_chunk(pb, Bb[it & 1], tid);
        __syncthreads();
        if (it + 1 < G2_NIT) {
            int nx = it + 1;
            int p = nx >> 3, kc = ks + (nx & 7) * 64;
            const __nv_bfloat16* Asrc = (p == 2) ? g_x2lo : g_x2hi;
            const __nv_bfloat16* Bsrc = (p == 1) ? g_w2t_lo : g_w2t_hi;
            fetch_chunk(Asrc, HC, m0, kc, pa, tid);
            fetch_chunk(Bsrc, HC, 0, kc, pb, tid);
        }
        mma_chunk(Ab[it & 1], Bb[it & 1], c, warp_m, warp_n, lane);
        __syncthreads();
    }

    float* outp = g_h2p + (size_t)blockIdx.y * MPAD * EMBED;
    #pragma unroll
    for (int mt = 0; mt < 2; mt++) {
        int r = warp_m * 32 + mt * 16 + g;
        #pragma unroll
        for (int nt = 0; nt < 8; nt++) {
            int col = warp_n * 64 + nt * 8 + tig * 2;
            float* cc = c[mt][nt];
            size_t base = (size_t)(m0 + r) * EMBED + col;
            *(float2*)(outp + base) = make_float2(cc[0], cc[1]);
            *(float2*)(outp + base + 8 * EMBED) = make_float2(cc[2], cc[3]);
        }
    }
}

// ===================== combine partials + al2 ===============================
__global__ void combine_kernel(const float* __restrict__ as2,
                               const float* __restrict__ ad2, int n) {
    int t = threadIdx.x;
    int row = blockIdx.x * 2 + (t >> 7);
    int col = t & 127;
    if (row >= n) return;
    size_t idx = (size_t)row * EMBED + col;
    float s = g_h2p[idx] + g_h2p[idx + (size_t)MPAD * EMBED]
            + g_h2p[idx + 2 * (size_t)MPAD * EMBED]
            + g_h2p[idx + 3 * (size_t)MPAD * EMBED];
    g_h2[idx] = __float2half(s);
    float a = s * __ldg(&as2[col]);
    float d = s * __ldg(&ad2[col]);
    #pragma unroll
    for (int o = 16; o > 0; o >>= 1) {
        a += __shfl_down_sync(0xffffffffu, a, o);
        d += __shfl_down_sync(0xffffffffu, d, o);
    }
    __shared__ float wa[8], wd[8];
    int w = t >> 5;
    if ((t & 31) == 0) { wa[w] = a; wd[w] = d; }
    __syncthreads();
    if ((t & 127) == 0) {
        int wb = (t >> 7) * 4;
        g_als2[row] = wa[wb] + wa[wb + 1] + wa[wb + 2] + wa[wb + 3];
        g_ald2[row] = wd[wb] + wd[wb + 1] + wd[wb + 2] + wd[wb + 3];
    }
}

// ===================== agg2 + classifier fused ==============================
__global__ void agg2cls_kernel(const float* __restrict__ b2,
                               const float* __restrict__ Wc,
                               const float* __restrict__ bc,
                               float* __restrict__ out) {
    int nno = blockIdx.x;
    int c = threadIdx.x;
    int beg = g_rowptr[nno], end = g_rowptr[nno + 1];
    float ad = g_ald2[nno];
    float m = M_SENT, s = 0.f, acc = 0.f;
    for (int j = beg; j < end; j++) {
        int src = __ldg(&g_col[j]);
        float lg = __ldg(&g_als2[src]) + ad;
        lg = lg > 0.f ? lg : NEG_SLOPE * lg;
        float hv = __half2float(__ldg(&g_h2[(size_t)src * EMBED + c]));
        if (lg > m) {
            float sc = (m == M_SENT) ? 0.f : __expf(m - lg);
            s = s * sc + 1.f;
            acc = acc * sc + hv;
            m = lg;
        } else {
            float p = __expf(lg - m);
            s += p;
            acc += p * hv;
        }
    }
    float val = acc / (s + 1e-16f) + b2[c];
    float part = val * __ldg(&Wc[c]);
    #pragma unroll
    for (int o = 16; o > 0; o >>= 1) part += __shfl_down_sync(0xffffffffu, part, o);
    __shared__ float ws[4];
    if ((c & 31) == 0) ws[c >> 5] = part;
    __syncthreads();
    if (c == 0) out[nno] = ws[0] + ws[1] + ws[2] + ws[3] + bc[0];
}

// ===================== launch ===============================================
extern "C" void kernel_launch(void* const* d_in, const int* in_sizes, int n_in,
                              void* d_out, int out_size) {
    const float* x   = (const float*)d_in[0];
    const void*  ei  = d_in[1];
    const float* W1  = (const float*)d_in[2];
    const float* as1 = (const float*)d_in[3];
    const float* ad1 = (const float*)d_in[4];
    const float* b1  = (const float*)d_in[5];
    const float* W2  = (const float*)d_in[6];
    const float* as2 = (const float*)d_in[7];
    const float* ad2 = (const float*)d_in[8];
    const float* b2  = (const float*)d_in[9];
    const float* Wc  = (const float*)d_in[10];
    const float* bc  = (const float*)d_in[11];
    float* out = (float*)d_out;

    int E = in_sizes[1] / 2;
    int n = in_sizes[0] / EMBED;
    int mtiles = (n + MT - 1) / MT;

    cudaFuncSetAttribute(expand1_kernel, cudaFuncAttributeMaxDynamicSharedMemorySize, G1_SMEM);
    cudaFuncSetAttribute(gemm2_kernel, cudaFuncAttributeMaxDynamicSharedMemorySize, G2_SMEM);

    prep_kernel<<<NB_WA + NB_W1 + NB_W2 + NB_DEG + 1, 256>>>(W1, W2, as1, ad1, ei);
    decode_count_kernel<<<(2 * E + 255) / 256, 256>>>(ei, E);
    scan_kernel<<<1, 1024>>>(n);
    fill_kernel<<<(E + n + 255) / 256, 256>>>(E, n);
    logits1_kernel<<<(n + 7) / 8, 256>>>(x, n);
    agg1_kernel<<<n, 256>>>(x);
    expand1_kernel<<<dim3(HEADS, mtiles), 256, G1_SMEM>>>(b1);
    gemm2_kernel<<<dim3(mtiles, KSPLIT), 256, G2_SMEM>>>();
    combine_kernel<<<(n + 1) / 2, 256>>>(as2, ad2, n);
    agg2cls_kernel<<<n, 128>>>(b2, Wc, bc, out);
}

// round 8
// speedup vs baseline: 1.0310x; 1.0310x over previous
#include <cuda_runtime.h>
#include <cuda_bf16.h>
#include <cuda_fp16.h>
#include <cstdint>

#define N_NODES 10000
#define EDGES   160000
#define EMBED   128
#define HEADS   16
#define HC      2048
#define NEG_SLOPE 0.2f
#define M_SENT  (-1e30f)
#define MT      128
#define MPAD    (79 * 128)
#define KSPLIT  4

// ===================== device scratch =======================================
__device__ int   g_src[EDGES];
__device__ int   g_dst[EDGES];
__device__ int   g_deg[N_NODES];          // zero-init; re-zeroed by fill each call
__device__ int   g_rowptr[N_NODES + 1];
__device__ int   g_cursor[N_NODES];
__device__ int   g_col[EDGES + N_NODES];

__device__ float g_waS[HEADS * EMBED];
__device__ float g_waD[HEADS * EMBED];
__device__ __nv_bfloat16 g_w1t_hi[(size_t)HC * EMBED];
__device__ __nv_bfloat16 g_w1t_lo[(size_t)HC * EMBED];
__device__ __nv_bfloat16 g_w2t_hi[(size_t)EMBED * HC];
__device__ __nv_bfloat16 g_w2t_lo[(size_t)EMBED * HC];
__device__ float g_als1[MPAD * HEADS];
__device__ float g_ald1[MPAD * HEADS];
__device__ __nv_bfloat16 g_axhi[(size_t)MPAD * HC];
__device__ __nv_bfloat16 g_axlo[(size_t)MPAD * HC];
__device__ __nv_bfloat16 g_x2hi[(size_t)MPAD * HC];
__device__ __nv_bfloat16 g_x2lo[(size_t)MPAD * HC];
__device__ float g_h2p[(size_t)KSPLIT * MPAD * EMBED];
__device__ __half g_h2[(size_t)MPAD * EMBED];
__device__ float g_als2[MPAD];
__device__ float g_ald2[MPAD];

// ===================== L0: prep + decode + count ============================
template <int R, int C>
__device__ void transpose_cv(const float* __restrict__ src,
                             __nv_bfloat16* __restrict__ dhi,
                             __nv_bfloat16* __restrict__ dlo, int bx, int by) {
    __shared__ float tile[32][33];
    int tx = threadIdx.x & 31, ty0 = threadIdx.x >> 5;
    #pragma unroll
    for (int j = 0; j < 4; j++) {
        int r = by * 32 + ty0 + j * 8, c = bx * 32 + tx;
        tile[ty0 + j * 8][tx] = src[(size_t)r * C + c];
    }
    __syncthreads();
    #pragma unroll
    for (int j = 0; j < 4; j++) {
        int rd = bx * 32 + ty0 + j * 8;
        int cd = by * 32 + tx;
        float v = tile[tx][ty0 + j * 8];
        __nv_bfloat16 h = __float2bfloat16(v);
        dhi[(size_t)rd * R + cd] = h;
        dlo[(size_t)rd * R + cd] = __float2bfloat16(v - __bfloat162float(h));
    }
}

#define NB_WA  16
#define NB_W1  256
#define NB_W2  256
#define NB_PRE (NB_WA + NB_W1 + NB_W2)

__global__ void prep_decode_kernel(const float* __restrict__ W1,
                                   const float* __restrict__ W2,
                                   const float* __restrict__ as1,
                                   const float* __restrict__ ad1,
                                   const void* __restrict__ ei, int E) {
    int b = blockIdx.x, t = threadIdx.x;
    if (b < NB_WA) {
        __shared__ float sa[EMBED], sd[EMBED];
        int h = b;
        if (t < 128) { sa[t] = as1[h * EMBED + t]; sd[t] = ad1[h * EMBED + t]; }
        __syncthreads();
        if (t < 128) {
            float ss = 0.f, ssd = 0.f;
            const float* wrow = W1 + (size_t)t * HC + h * EMBED;
            #pragma unroll 4
            for (int c = 0; c < EMBED; c++) {
                float w = wrow[c];
                ss += w * sa[c];
                ssd += w * sd[c];
            }
            g_waS[h * EMBED + t] = ss;
            g_waD[h * EMBED + t] = ssd;
        }
        return;
    }
    b -= NB_WA;
    if (b < NB_W1) { transpose_cv<128, 2048>(W1, g_w1t_hi, g_w1t_lo, b & 63, b >> 6); return; }
    b -= NB_W1;
    if (b < NB_W2) { transpose_cv<2048, 128>(W2, g_w2t_hi, g_w2t_lo, b & 3, b >> 2); return; }
    b -= NB_W2;
    // decode + count with block-local dtype detect
    const long long* p64 = (const long long*)ei;
    long long pv = p64[t];                       // 256 probes
    int ok = (pv >= 0 && pv < N_NODES);
    int is64 = __syncthreads_and(ok);
    int i = b * 256 + t;
    if (i >= 2 * E) return;
    int vi = is64 ? (int)p64[i] : ((const int*)ei)[i];
    if (i < E) g_src[i] = vi;
    else { g_dst[i - E] = vi; atomicAdd(&g_deg[vi], 1); }
}

// ===================== L1: scan (block 0, self-loop implicit) + logits1 =====
__global__ void scan_logits_kernel(const float* __restrict__ x, int n) {
    int t = threadIdx.x;
    if (blockIdx.x == 0) {
        __shared__ int wsum[32];
        int CH = (n + 1023) / 1024;
        int base = t * CH;
        int s = 0;
        for (int k = 0; k < CH; k++) { int idx = base + k; if (idx < n) s += g_deg[idx] + 1; }
        int lane = t & 31, wid = t >> 5;
        int v = s;
        #pragma unroll
        for (int o = 1; o < 32; o <<= 1) {
            int t2 = __shfl_up_sync(0xffffffffu, v, o);
            if (lane >= o) v += t2;
        }
        if (lane == 31) wsum[wid] = v;
        __syncthreads();
        if (wid == 0) {
            int w = wsum[lane];
            #pragma unroll
            for (int o = 1; o < 32; o <<= 1) {
                int t2 = __shfl_up_sync(0xffffffffu, w, o);
                if (lane >= o) w += t2;
            }
            wsum[lane] = w;
        }
        __syncthreads();
        int excl = v - s + (wid ? wsum[wid - 1] : 0);
        int running = excl;
        for (int k = 0; k < CH; k++) {
            int idx = base + k;
            if (idx < n) {
                g_rowptr[idx] = running;
                g_cursor[idx] = running;
                running += g_deg[idx] + 1;
            }
        }
        if (t == 0) g_rowptr[n] = wsum[31];
        return;
    }
    // logits: 32 warps, one node each
    int node = (blockIdx.x - 1) * 32 + (t >> 5);
    if (node >= n) return;
    int lane = t & 31;
    float4 xv = ((const float4*)(x + (size_t)node * EMBED))[lane];
    #pragma unroll
    for (int h = 0; h < HEADS; h++) {
        float4 wS = ((const float4*)(g_waS + h * EMBED))[lane];
        float4 wD = ((const float4*)(g_waD + h * EMBED))[lane];
        float ss = xv.x * wS.x + xv.y * wS.y + xv.z * wS.z + xv.w * wS.w;
        float sd = xv.x * wD.x + xv.y * wD.y + xv.z * wD.z + xv.w * wD.w;
        #pragma unroll
        for (int o = 16; o > 0; o >>= 1) {
            ss += __shfl_xor_sync(0xffffffffu, ss, o);
            sd += __shfl_xor_sync(0xffffffffu, sd, o);
        }
        if (lane == 0) {
            g_als1[node * HEADS + h] = ss;
            g_ald1[node * HEADS + h] = sd;
        }
    }
}

// ===================== L2: fill (+ deg self-clean) ==========================
__global__ void fill_kernel(int E, int n) {
    int i = blockIdx.x * blockDim.x + threadIdx.x;
    if (i < E) {
        int d = g_dst[i];
        int pos = atomicAdd(&g_cursor[d], 1);
        g_col[pos] = g_src[i];
    } else if (i < E + n) {
        int v = i - E;
        int pos = atomicAdd(&g_cursor[v], 1);
        g_col[pos] = v;
        g_deg[v] = 0;          // self-clean for next call (zero-init on first)
    }
}

// ===================== L3 (PROFILED): agg1, 2-phase softmax =================
__global__ void agg1_kernel(const float* __restrict__ x) {
    int nno = blockIdx.x;
    int t = threadIdx.x;               // 256 = 16 heads x 16 channel-threads
    int h = t >> 4, c = t & 15;
    int beg = g_rowptr[nno];
    int deg = g_rowptr[nno + 1] - beg;
    float ad = g_ald1[nno * HEADS + h];

    // phase 1: edge-strided (m, s)
    float lm = M_SENT, ls = 0.f;
    for (int j = c; j < deg; j += 16) {
        int src = __ldg(&g_col[beg + j]);
        float lg = __ldg(&g_als1[src * HEADS + h]) + ad;
        lg = lg > 0.f ? lg : NEG_SLOPE * lg;
        if (lg > lm) { ls = ls * __expf(lm - lg) + 1.f; lm = lg; }
        else ls += __expf(lg - lm);
    }
    #pragma unroll
    for (int o = 8; o > 0; o >>= 1) {
        float om = __shfl_xor_sync(0xffffffffu, lm, o);
        float os = __shfl_xor_sync(0xffffffffu, ls, o);
        float nm = fmaxf(lm, om);
        ls = ls * __expf(lm - nm) + os * __expf(om - nm);
        lm = nm;
    }
    float m = lm;
    float inv = 1.f / (ls + 1e-16f);

    // phase 2: branch-free weighted accumulation
    float a[8];
    #pragma unroll
    for (int i = 0; i < 8; i++) a[i] = 0.f;
    for (int j = 0; j < deg; j++) {
        int src = __ldg(&g_col[beg + j]);
        float lg = __ldg(&g_als1[src * HEADS + h]) + ad;
        lg = lg > 0.f ? lg : NEG_SLOPE * lg;
        float w = __expf(lg - m) * inv;
        float4 x0 = __ldg((const float4*)(x + (size_t)src * EMBED + c * 8));
        float4 x1 = __ldg((const float4*)(x + (size_t)src * EMBED + c * 8 + 4));
        a[0] += w * x0.x; a[1] += w * x0.y; a[2] += w * x0.z; a[3] += w * x0.w;
        a[4] += w * x1.x; a[5] += w * x1.y; a[6] += w * x1.z; a[7] += w * x1.w;
    }
    __align__(16) __nv_bfloat16 hb[8], lb[8];
    #pragma unroll
    for (int i = 0; i < 8; i++) {
        __nv_bfloat16 hi = __float2bfloat16(a[i]);
        hb[i] = hi;
        lb[i] = __float2bfloat16(a[i] - __bfloat162float(hi));
    }
    size_t off = (size_t)nno * HC + h * EMBED + c * 8;
    *(float4*)(g_axhi + off) = *(float4*)hb;
    *(float4*)(g_axlo + off) = *(float4*)lb;
}

// ===================== mma.sync GEMM machinery ==============================
#define SKW 72
#define CHUNK_B (128 * SKW * 2)

__device__ __forceinline__ void mma16816(float* c, const uint32_t* a, const uint32_t* b) {
    asm volatile("mma.sync.aligned.m16n8k16.row.col.f32.bf16.bf16.f32 "
        "{%0,%1,%2,%3}, {%4,%5,%6,%7}, {%8,%9}, {%0,%1,%2,%3};"
        : "+f"(c[0]), "+f"(c[1]), "+f"(c[2]), "+f"(c[3])
        : "r"(a[0]), "r"(a[1]), "r"(a[2]), "r"(a[3]), "r"(b[0]), "r"(b[1]));
}

__device__ __forceinline__ void fetch_chunk(const __nv_bfloat16* __restrict__ src,
                                            int ld, int row0, int k0,
                                            float4* r, int tid) {
    #pragma unroll
    for (int i = 0; i < 4; i++) {
        int c = tid + i * 256;
        int row = c >> 3;
        int kk = (c & 7) * 8;
        r[i] = *(const float4*)(src + (size_t)(row0 + row) * ld + k0 + kk);
    }
}

__device__ __forceinline__ void stash_chunk(const float4* r,
                                            __nv_bfloat16 (*S)[SKW], int tid) {
    #pragma unroll
    for (int i = 0; i < 4; i++) {
        int c = tid + i * 256;
        int row = c >> 3;
        int kk = (c & 7) * 8;
        *(float4*)&S[row][kk] = r[i];
    }
}

__device__ __forceinline__ void mma_chunk(const __nv_bfloat16 (*As)[SKW],
                                          const __nv_bfloat16 (*Bs)[SKW],
                                          float c[2][8][4],
                                          int warp_m, int warp_n, int lane) {
    int g = lane >> 2, tig = lane & 3;
    #pragma unroll
    for (int ks = 0; ks < 4; ks++) {
        int k0 = ks * 16;
        uint32_t a[2][4], b[8][2];
        #pragma unroll
        for (int mt = 0; mt < 2; mt++) {
            int r = warp_m * 32 + mt * 16 + g;
            a[mt][0] = *(const uint32_t*)&As[r][k0 + tig * 2];
            a[mt][1] = *(const uint32_t*)&As[r + 8][k0 + tig * 2];
            a[mt][2] = *(const uint32_t*)&As[r][k0 + tig * 2 + 8];
            a[mt][3] = *(const uint32_t*)&As[r + 8][k0 + tig * 2 + 8];
        }
        #pragma unroll
        for (int nt = 0; nt < 8; nt++) {
            int n = warp_n * 64 + nt * 8 + g;
            b[nt][0] = *(const uint32_t*)&Bs[n][k0 + tig * 2];
            b[nt][1] = *(const uint32_t*)&Bs[n][k0 + tig * 2 + 8];
        }
        #pragma unroll
        for (int mt = 0; mt < 2; mt++)
            #pragma unroll
            for (int nt = 0; nt < 8; nt++)
                mma16816(c[mt][nt], a[mt], b[nt]);
    }
}

// ===================== L4: expand1 = ELU(aggx @ W1_h + b1) ==================
#define G1_SMEM (4 * CHUNK_B + 128 * 4)

__global__ __launch_bounds__(256) void expand1_kernel(const float* __restrict__ b1) {
    extern __shared__ char dsm[];
    __nv_bfloat16 (*Ab[2])[SKW] = {(__nv_bfloat16(*)[SKW])dsm,
                                   (__nv_bfloat16(*)[SKW])(dsm + 2 * CHUNK_B)};
    __nv_bfloat16 (*Bb[2])[SKW] = {(__nv_bfloat16(*)[SKW])(dsm + CHUNK_B),
                                   (__nv_bfloat16(*)[SKW])(dsm + 3 * CHUNK_B)};
    float* s_b = (float*)(dsm + 4 * CHUNK_B);

    int tid = threadIdx.x;
    int wid = tid >> 5, lane = tid & 31;
    int warp_m = wid & 3, warp_n = wid >> 2;
    int g = lane >> 2, tig = lane & 3;
    int h = blockIdx.x;
    int m0 = blockIdx.y * MT;

    if (tid < 128) s_b[tid] = b1[h * EMBED + tid];

    float c[2][8][4];
    #pragma unroll
    for (int mt = 0; mt < 2; mt++)
        #pragma unroll
        for (int nt = 0; nt < 8; nt++)
            #pragma unroll
            for (int i = 0; i < 4; i++) c[mt][nt][i] = 0.f;

    float4 pa[4], pb[4];
    fetch_chunk(g_axhi, HC, m0, h * EMBED, pa, tid);
    fetch_chunk(g_w1t_hi, EMBED, h * 128, 0, pb, tid);
    #pragma unroll
    for (int it = 0; it < 6; it++) {
        stash_chunk(pa, Ab[it & 1], tid);
        stash_chunk(pb, Bb[it & 1], tid);
        __syncthreads();
        if (it + 1 < 6) {
            int nx = it + 1;
            int p = nx >> 1, kc = (nx & 1) * 64;
            const __nv_bfloat16* Asrc = (p == 2) ? g_axlo : g_axhi;
            const __nv_bfloat16* Bsrc = (p == 1) ? g_w1t_lo : g_w1t_hi;
            fetch_chunk(Asrc, HC, m0, h * EMBED + kc, pa, tid);
            fetch_chunk(Bsrc, EMBED, h * 128, kc, pb, tid);
        }
        mma_chunk(Ab[it & 1], Bb[it & 1], c, warp_m, warp_n, lane);
        __syncthreads();
    }

    #pragma unroll
    for (int mt = 0; mt < 2; mt++) {
        int r = warp_m * 32 + mt * 16 + g;
        #pragma unroll
        for (int nt = 0; nt < 8; nt++) {
            int col = warp_n * 64 + nt * 8 + tig * 2;
            float* cc = c[mt][nt];
            #pragma unroll
            for (int q = 0; q < 2; q++) {
                float v0 = cc[q * 2 + 0] + s_b[col];
                float v1 = cc[q * 2 + 1] + s_b[col + 1];
                v0 = v0 > 0.f ? v0 : (__expf(v0) - 1.f);
                v1 = v1 > 0.f ? v1 : (__expf(v1) - 1.f);
                __nv_bfloat16 h0 = __float2bfloat16(v0);
                __nv_bfloat16 h1 = __float2bfloat16(v1);
                __nv_bfloat162 hh; hh.x = h0; hh.y = h1;
                __nv_bfloat162 ll;
                ll.x = __float2bfloat16(v0 - __bfloat162float(h0));
                ll.y = __float2bfloat16(v1 - __bfloat162float(h1));
                size_t base = (size_t)(m0 + r + q * 8) * HC + h * EMBED + col;
                *(__nv_bfloat162*)(g_x2hi + base) = hh;
                *(__nv_bfloat162*)(g_x2lo + base) = ll;
            }
        }
    }
}

// ===================== L5: GEMM2 K-split ====================================
#define G2_SMEM (4 * CHUNK_B)
#define G2_NIT  24

__global__ __launch_bounds__(256) void gemm2_kernel() {
    extern __shared__ char dsm[];
    __nv_bfloat16 (*Ab[2])[SKW] = {(__nv_bfloat16(*)[SKW])dsm,
                                   (__nv_bfloat16(*)[SKW])(dsm + 2 * CHUNK_B)};
    __nv_bfloat16 (*Bb[2])[SKW] = {(__nv_bfloat16(*)[SKW])(dsm + CHUNK_B),
                                   (__nv_bfloat16(*)[SKW])(dsm + 3 * CHUNK_B)};

    int tid = threadIdx.x;
    int wid = tid >> 5, lane = tid & 31;
    int warp_m = wid & 3, warp_n = wid >> 2;
    int g = lane >> 2, tig = lane & 3;
    int m0 = blockIdx.x * MT;
    int ks = blockIdx.y * 512;

    float c[2][8][4];
    #pragma unroll
    for (int mt = 0; mt < 2; mt++)
        #pragma unroll
        for (int nt = 0; nt < 8; nt++)
            #pragma unroll
            for (int i = 0; i < 4; i++) c[mt][nt][i] = 0.f;

    float4 pa[4], pb[4];
    fetch_chunk(g_x2hi, HC, m0, ks, pa, tid);
    fetch_chunk(g_w2t_hi, HC, 0, ks, pb, tid);
    for (int it = 0; it < G2_NIT; it++) {
        stash_chunk(pa, Ab[it & 1], tid);
        stash_chunk(pb, Bb[it & 1], tid);
        __syncthreads();
        if (it + 1 < G2_NIT) {
            int nx = it + 1;
            int p = nx >> 3, kc = ks + (nx & 7) * 64;
            const __nv_bfloat16* Asrc = (p == 2) ? g_x2lo : g_x2hi;
            const __nv_bfloat16* Bsrc = (p == 1) ? g_w2t_lo : g_w2t_hi;
            fetch_chunk(Asrc, HC, m0, kc, pa, tid);
            fetch_chunk(Bsrc, HC, 0, kc, pb, tid);
        }
        mma_chunk(Ab[it & 1], Bb[it & 1], c, warp_m, warp_n, lane);
        __syncthreads();
    }

    float* outp = g_h2p + (size_t)blockIdx.y * MPAD * EMBED;
    #pragma unroll
    for (int mt = 0; mt < 2; mt++) {
        int r = warp_m * 32 + mt * 16 + g;
        #pragma unroll
        for (int nt = 0; nt < 8; nt++) {
            int col = warp_n * 64 + nt * 8 + tig * 2;
            float* cc = c[mt][nt];
            size_t base = (size_t)(m0 + r) * EMBED + col;
            *(float2*)(outp + base) = make_float2(cc[0], cc[1]);
            *(float2*)(outp + base + 8 * EMBED) = make_float2(cc[2], cc[3]);
        }
    }
}

// ===================== L6: combine + al2 ====================================
__global__ void combine_kernel(const float* __restrict__ as2,
                               const float* __restrict__ ad2, int n) {
    int t = threadIdx.x;
    int row = blockIdx.x * 2 + (t >> 7);
    int col = t & 127;
    if (row >= n) return;
    size_t idx = (size_t)row * EMBED + col;
    float s = g_h2p[idx] + g_h2p[idx + (size_t)MPAD * EMBED]
            + g_h2p[idx + 2 * (size_t)MPAD * EMBED]
            + g_h2p[idx + 3 * (size_t)MPAD * EMBED];
    g_h2[idx] = __float2half(s);
    float a = s * __ldg(&as2[col]);
    float d = s * __ldg(&ad2[col]);
    #pragma unroll
    for (int o = 16; o > 0; o >>= 1) {
        a += __shfl_down_sync(0xffffffffu, a, o);
        d += __shfl_down_sync(0xffffffffu, d, o);
    }
    __shared__ float wa[8], wd[8];
    int w = t >> 5;
    if ((t & 31) == 0) { wa[w] = a; wd[w] = d; }
    __syncthreads();
    if ((t & 127) == 0) {
        int wb = (t >> 7) * 4;
        g_als2[row] = wa[wb] + wa[wb + 1] + wa[wb + 2] + wa[wb + 3];
        g_ald2[row] = wd[wb] + wd[wb + 1] + wd[wb + 2] + wd[wb + 3];
    }
}

// ===================== L7: agg2 + classifier, 2-phase =======================
__global__ void agg2cls_kernel(const float* __restrict__ b2,
                               const float* __restrict__ Wc,
                               const float* __restrict__ bc,
                               float* __restrict__ out) {
    int nno = blockIdx.x;
    int t = threadIdx.x;               // 128
    int beg = g_rowptr[nno];
    int deg = g_rowptr[nno + 1] - beg;
    float ad = g_ald2[nno];

    float lm = M_SENT, ls = 0.f;
    for (int j = t; j < deg; j += 128) {
        int src = __ldg(&g_col[beg + j]);
        float lg = __ldg(&g_als2[src]) + ad;
        lg = lg > 0.f ? lg : NEG_SLOPE * lg;
        if (lg > lm) { ls = ls * __expf(lm - lg) + 1.f; lm = lg; }
        else ls += __expf(lg - lm);
    }
    #pragma unroll
    for (int o = 16; o > 0; o >>= 1) {
        float om = __shfl_xor_sync(0xffffffffu, lm, o);
        float os = __shfl_xor_sync(0xffffffffu, ls, o);
        float nm = fmaxf(lm, om);
        ls = ls * __expf(lm - nm) + os * __expf(om - nm);
        lm = nm;
    }
    __shared__ float sm[4], ssum[4];
    if ((t & 31) == 0) { sm[t >> 5] = lm; ssum[t >> 5] = ls; }
    __syncthreads();
    float m = fmaxf(fmaxf(sm[0], sm[1]), fmaxf(sm[2], sm[3]));
    float s = ssum[0] * __expf(sm[0] - m) + ssum[1] * __expf(sm[1] - m)
            + ssum[2] * __expf(sm[2] - m) + ssum[3] * __expf(sm[3] - m);
    float inv = 1.f / (s + 1e-16f);

    float acc = 0.f;
    for (int j = 0; j < deg; j++) {
        int src = __ldg(&g_col[beg + j]);
        float lg = __ldg(&g_als2[src]) + ad;
        lg = lg > 0.f ? lg : NEG_SLOPE * lg;
        float w = __expf(lg - m) * inv;
        acc += w * __half2float(__ldg(&g_h2[(size_t)src * EMBED + t]));
    }
    float val = acc + b2[t];
    float part = val * __ldg(&Wc[t]);
    #pragma unroll
    for (int o = 16; o > 0; o >>= 1) part += __shfl_down_sync(0xffffffffu, part, o);
    __shared__ float ws[4];
    if ((t & 31) == 0) ws[t >> 5] = part;
    __syncthreads();
    if (t == 0) out[nno] = ws[0] + ws[1] + ws[2] + ws[3] + bc[0];
}

// ===================== launch ===============================================
extern "C" void kernel_launch(void* const* d_in, const int* in_sizes, int n_in,
                              void* d_out, int out_size) {
    const float* x   = (const float*)d_in[0];
    const void*  ei  = d_in[1];
    const float* W1  = (const float*)d_in[2];
    const float* as1 = (const float*)d_in[3];
    const float* ad1 = (const float*)d_in[4];
    const float* b1  = (const float*)d_in[5];
    const float* W2  = (const float*)d_in[6];
    const float* as2 = (const float*)d_in[7];
    const float* ad2 = (const float*)d_in[8];
    const float* b2  = (const float*)d_in[9];
    const float* Wc  = (const float*)d_in[10];
    const float* bc  = (const float*)d_in[11];
    float* out = (float*)d_out;

    int E = in_sizes[1] / 2;
    int n = in_sizes[0] / EMBED;
    int mtiles = (n + MT - 1) / MT;

    cudaFuncSetAttribute(expand1_kernel, cudaFuncAttributeMaxDynamicSharedMemorySize, G1_SMEM);
    cudaFuncSetAttribute(gemm2_kernel, cudaFuncAttributeMaxDynamicSharedMemorySize, G2_SMEM);

    int decode_blocks = (2 * E + 255) / 256;
    prep_decode_kernel<<<NB_PRE + decode_blocks, 256>>>(W1, W2, as1, ad1, ei, E); // 0
    scan_logits_kernel<<<1 + (n + 31) / 32, 1024>>>(x, n);                        // 1
    fill_kernel<<<(E + n + 255) / 256, 256>>>(E, n);                              // 2
    agg1_kernel<<<n, 256>>>(x);                                                   // 3 <- profiled
    expand1_kernel<<<dim3(HEADS, mtiles), 256, G1_SMEM>>>(b1);                    // 4
    gemm2_kernel<<<dim3(mtiles, KSPLIT), 256, G2_SMEM>>>();                       // 5
    combine_kernel<<<(n + 1) / 2, 256>>>(as2, ad2, n);                            // 6
    agg2cls_kernel<<<n, 128>>>(b2, Wc, bc, out);                                  // 7
}

// round 9
// speedup vs baseline: 1.1973x; 1.1613x over previous
#include <cuda_runtime.h>
#include <cuda_bf16.h>
#include <cuda_fp16.h>
#include <cstdint>

#define N_NODES 10000
#define EDGES   160000
#define EMBED   128
#define HEADS   16
#define HC      2048
#define NEG_SLOPE 0.2f
#define M_SENT  (-1e30f)
#define MT      128
#define MPAD    (79 * 128)
#define KSPLIT  4

// ===================== device scratch =======================================
__device__ int   g_src[EDGES];
__device__ int   g_dst[EDGES];
__device__ int   g_deg[N_NODES];          // zero-init; re-zeroed by fill each call
__device__ int   g_rowptr[N_NODES + 1];
__device__ int   g_cursor[N_NODES];
__device__ int   g_col[EDGES + N_NODES];

__device__ float g_waS[HEADS * EMBED];
__device__ float g_waD[HEADS * EMBED];
__device__ __nv_bfloat16 g_w1t_hi[(size_t)HC * EMBED];
__device__ __nv_bfloat16 g_w1t_lo[(size_t)HC * EMBED];
__device__ __nv_bfloat16 g_w2t_hi[(size_t)EMBED * HC];
__device__ __nv_bfloat16 g_w2t_lo[(size_t)EMBED * HC];
__device__ float g_als1[MPAD * HEADS];
__device__ float g_ald1[MPAD * HEADS];
__device__ __nv_bfloat16 g_axhi[(size_t)MPAD * HC];
__device__ __nv_bfloat16 g_axlo[(size_t)MPAD * HC];
__device__ __nv_bfloat16 g_x2hi[(size_t)MPAD * HC];
__device__ __nv_bfloat16 g_x2lo[(size_t)MPAD * HC];
__device__ float g_h2p[(size_t)KSPLIT * MPAD * EMBED];
__device__ __half g_h2[(size_t)MPAD * EMBED];
__device__ float g_als2[MPAD];
__device__ float g_ald2[MPAD];

// ===================== L0: prep + decode + count ============================
template <int R, int C>
__device__ void transpose_cv(const float* __restrict__ src,
                             __nv_bfloat16* __restrict__ dhi,
                             __nv_bfloat16* __restrict__ dlo, int bx, int by) {
    __shared__ float tile[32][33];
    int tx = threadIdx.x & 31, ty0 = threadIdx.x >> 5;
    #pragma unroll
    for (int j = 0; j < 4; j++) {
        int r = by * 32 + ty0 + j * 8, c = bx * 32 + tx;
        tile[ty0 + j * 8][tx] = src[(size_t)r * C + c];
    }
    __syncthreads();
    #pragma unroll
    for (int j = 0; j < 4; j++) {
        int rd = bx * 32 + ty0 + j * 8;
        int cd = by * 32 + tx;
        float v = tile[tx][ty0 + j * 8];
        __nv_bfloat16 h = __float2bfloat16(v);
        dhi[(size_t)rd * R + cd] = h;
        dlo[(size_t)rd * R + cd] = __float2bfloat16(v - __bfloat162float(h));
    }
}

#define NB_WA  16
#define NB_W1  256
#define NB_W2  256
#define NB_PRE (NB_WA + NB_W1 + NB_W2)

__global__ void prep_decode_kernel(const float* __restrict__ W1,
                                   const float* __restrict__ W2,
                                   const float* __restrict__ as1,
                                   const float* __restrict__ ad1,
                                   const void* __restrict__ ei, int E) {
    int b = blockIdx.x, t = threadIdx.x;
    if (b < NB_WA) {
        __shared__ float sa[EMBED], sd[EMBED];
        int h = b;
        if (t < 128) { sa[t] = as1[h * EMBED + t]; sd[t] = ad1[h * EMBED + t]; }
        __syncthreads();
        if (t < 128) {
            float ss = 0.f, ssd = 0.f;
            const float* wrow = W1 + (size_t)t * HC + h * EMBED;
            #pragma unroll 4
            for (int c = 0; c < EMBED; c++) {
                float w = wrow[c];
                ss += w * sa[c];
                ssd += w * sd[c];
            }
            g_waS[h * EMBED + t] = ss;
            g_waD[h * EMBED + t] = ssd;
        }
        return;
    }
    b -= NB_WA;
    if (b < NB_W1) { transpose_cv<128, 2048>(W1, g_w1t_hi, g_w1t_lo, b & 63, b >> 6); return; }
    b -= NB_W1;
    if (b < NB_W2) { transpose_cv<2048, 128>(W2, g_w2t_hi, g_w2t_lo, b & 3, b >> 2); return; }
    b -= NB_W2;
    const long long* p64 = (const long long*)ei;
    long long pv = p64[t];
    int ok = (pv >= 0 && pv < N_NODES);
    int is64 = __syncthreads_and(ok);
    int i = b * 256 + t;
    if (i >= 2 * E) return;
    int vi = is64 ? (int)p64[i] : ((const int*)ei)[i];
    if (i < E) g_src[i] = vi;
    else { g_dst[i - E] = vi; atomicAdd(&g_deg[vi], 1); }
}

// ===================== L1: scan (block 0) + logits1 =========================
__global__ void scan_logits_kernel(const float* __restrict__ x, int n) {
    int t = threadIdx.x;
    if (blockIdx.x == 0) {
        __shared__ int wsum[32];
        int CH = (n + 1023) / 1024;
        int base = t * CH;
        int s = 0;
        for (int k = 0; k < CH; k++) { int idx = base + k; if (idx < n) s += g_deg[idx] + 1; }
        int lane = t & 31, wid = t >> 5;
        int v = s;
        #pragma unroll
        for (int o = 1; o < 32; o <<= 1) {
            int t2 = __shfl_up_sync(0xffffffffu, v, o);
            if (lane >= o) v += t2;
        }
        if (lane == 31) wsum[wid] = v;
        __syncthreads();
        if (wid == 0) {
            int w = wsum[lane];
            #pragma unroll
            for (int o = 1; o < 32; o <<= 1) {
                int t2 = __shfl_up_sync(0xffffffffu, w, o);
                if (lane >= o) w += t2;
            }
            wsum[lane] = w;
        }
        __syncthreads();
        int excl = v - s + (wid ? wsum[wid - 1] : 0);
        int running = excl;
        for (int k = 0; k < CH; k++) {
            int idx = base + k;
            if (idx < n) {
                g_rowptr[idx] = running;
                g_cursor[idx] = running;
                running += g_deg[idx] + 1;
            }
        }
        if (t == 0) g_rowptr[n] = wsum[31];
        return;
    }
    int node = (blockIdx.x - 1) * 32 + (t >> 5);
    if (node >= n) return;
    int lane = t & 31;
    float4 xv = ((const float4*)(x + (size_t)node * EMBED))[lane];
    #pragma unroll
    for (int h = 0; h < HEADS; h++) {
        float4 wS = ((const float4*)(g_waS + h * EMBED))[lane];
        float4 wD = ((const float4*)(g_waD + h * EMBED))[lane];
        float ss = xv.x * wS.x + xv.y * wS.y + xv.z * wS.z + xv.w * wS.w;
        float sd = xv.x * wD.x + xv.y * wD.y + xv.z * wD.z + xv.w * wD.w;
        #pragma unroll
        for (int o = 16; o > 0; o >>= 1) {
            ss += __shfl_xor_sync(0xffffffffu, ss, o);
            sd += __shfl_xor_sync(0xffffffffu, sd, o);
        }
        if (lane == 0) {
            g_als1[node * HEADS + h] = ss;
            g_ald1[node * HEADS + h] = sd;
        }
    }
}

// ===================== L2: fill (+ deg self-clean) ==========================
__global__ void fill_kernel(int E, int n) {
    int i = blockIdx.x * blockDim.x + threadIdx.x;
    if (i < E) {
        int d = g_dst[i];
        int pos = atomicAdd(&g_cursor[d], 1);
        g_col[pos] = g_src[i];
    } else if (i < E + n) {
        int v = i - E;
        int pos = atomicAdd(&g_cursor[v], 1);
        g_col[pos] = v;
        g_deg[v] = 0;
    }
}

// ===================== L3 (PROFILED): agg1, head-shared gather ==============
__global__ __launch_bounds__(128) void agg1_kernel(const float* __restrict__ x) {
    int nno = blockIdx.x;
    int t = threadIdx.x;               // 128 threads; phase2: t = channel
    int beg = g_rowptr[nno];
    int deg = g_rowptr[nno + 1] - beg;
    int h = t & 15, sub = t >> 4;      // phase1 roles

    __shared__ float s_ad[16], s_m[16], s_inv[16];
    __shared__ float s_pm[4][16], s_ps[4][16];
    __shared__ int   s_src[32];
    __shared__ float sw[32][16];

    if (t < 16) s_ad[t] = g_ald1[nno * HEADS + t];
    __syncthreads();

    // phase 1: per-head (m, s), 8-way edge parallel
    float ad = s_ad[h];
    float lm = M_SENT, ls = 0.f;
    for (int j = sub; j < deg; j += 8) {
        int src = __ldg(&g_col[beg + j]);
        float lg = __ldg(&g_als1[src * HEADS + h]) + ad;
        lg = lg > 0.f ? lg : NEG_SLOPE * lg;
        if (lg > lm) { ls = ls * __expf(lm - lg) + 1.f; lm = lg; }
        else ls += __expf(lg - lm);
    }
    {   // combine sub-pair within warp (lane xor 16 has same h)
        float om = __shfl_xor_sync(0xffffffffu, lm, 16);
        float os = __shfl_xor_sync(0xffffffffu, ls, 16);
        float nm = fmaxf(lm, om);
        ls = ls * __expf(lm - nm) + os * __expf(om - nm);
        lm = nm;
    }
    int warp = t >> 5;
    if ((t & 31) < 16) { s_pm[warp][h] = lm; s_ps[warp][h] = ls; }
    __syncthreads();
    if (t < 16) {
        float m0 = s_pm[0][t], m1 = s_pm[1][t], m2 = s_pm[2][t], m3 = s_pm[3][t];
        float mm = fmaxf(fmaxf(m0, m1), fmaxf(m2, m3));
        float ss = s_ps[0][t] * __expf(m0 - mm) + s_ps[1][t] * __expf(m1 - mm)
                 + s_ps[2][t] * __expf(m2 - mm) + s_ps[3][t] * __expf(m3 - mm);
        s_m[t] = mm;
        s_inv[t] = 1.f / (ss + 1e-16f);
    }
    __syncthreads();

    // phase 2: tiles of 32 edges; weights staged in shared, x loaded once/edge
    float acc[16];
    #pragma unroll
    for (int i = 0; i < 16; i++) acc[i] = 0.f;

    for (int e0 = 0; e0 < deg; e0 += 32) {
        int ne = min(32, deg - e0);
        if (t < ne) s_src[t] = __ldg(&g_col[beg + e0 + t]);
        __syncthreads();
        for (int k = t; k < ne * 16; k += 128) {
            int e = k >> 4, hh = k & 15;   // hh == t&15 (constant per thread)
            int src = s_src[e];
            float lg = __ldg(&g_als1[src * HEADS + hh]) + s_ad[hh];
            lg = lg > 0.f ? lg : NEG_SLOPE * lg;
            sw[e][hh] = __expf(lg - s_m[hh]) * s_inv[hh];
        }
        __syncthreads();
        for (int e = 0; e < ne; e++) {
            float xv = __ldg(&x[(size_t)s_src[e] * EMBED + t]);
            float4 w0 = *(float4*)&sw[e][0];
            float4 w1 = *(float4*)&sw[e][4];
            float4 w2 = *(float4*)&sw[e][8];
            float4 w3 = *(float4*)&sw[e][12];
            acc[0]  += w0.x * xv;  acc[1]  += w0.y * xv;
            acc[2]  += w0.z * xv;  acc[3]  += w0.w * xv;
            acc[4]  += w1.x * xv;  acc[5]  += w1.y * xv;
            acc[6]  += w1.z * xv;  acc[7]  += w1.w * xv;
            acc[8]  += w2.x * xv;  acc[9]  += w2.y * xv;
            acc[10] += w2.z * xv;  acc[11] += w2.w * xv;
            acc[12] += w3.x * xv;  acc[13] += w3.y * xv;
            acc[14] += w3.z * xv;  acc[15] += w3.w * xv;
        }
        __syncthreads();
    }

    #pragma unroll
    for (int i = 0; i < 16; i++) {
        float v = acc[i];
        __nv_bfloat16 hi = __float2bfloat16(v);
        __nv_bfloat16 lo = __float2bfloat16(v - __bfloat162float(hi));
        g_axhi[(size_t)nno * HC + i * EMBED + t] = hi;
        g_axlo[(size_t)nno * HC + i * EMBED + t] = lo;
    }
}

// ===================== mma.sync GEMM machinery ==============================
#define SKW 72
#define CHUNK_B (128 * SKW * 2)

__device__ __forceinline__ void mma16816(float* c, const uint32_t* a, const uint32_t* b) {
    asm volatile("mma.sync.aligned.m16n8k16.row.col.f32.bf16.bf16.f32 "
        "{%0,%1,%2,%3}, {%4,%5,%6,%7}, {%8,%9}, {%0,%1,%2,%3};"
        : "+f"(c[0]), "+f"(c[1]), "+f"(c[2]), "+f"(c[3])
        : "r"(a[0]), "r"(a[1]), "r"(a[2]), "r"(a[3]), "r"(b[0]), "r"(b[1]));
}

__device__ __forceinline__ void fetch_chunk(const __nv_bfloat16* __restrict__ src,
                                            int ld, int row0, int k0,
                                            float4* r, int tid) {
    #pragma unroll
    for (int i = 0; i < 4; i++) {
        int c = tid + i * 256;
        int row = c >> 3;
        int kk = (c & 7) * 8;
        r[i] = *(const float4*)(src + (size_t)(row0 + row) * ld + k0 + kk);
    }
}

__device__ __forceinline__ void stash_chunk(const float4* r,
                                            __nv_bfloat16 (*S)[SKW], int tid) {
    #pragma unroll
    for (int i = 0; i < 4; i++) {
        int c = tid + i * 256;
        int row = c >> 3;
        int kk = (c & 7) * 8;
        *(float4*)&S[row][kk] = r[i];
    }
}

__device__ __forceinline__ void mma_chunk(const __nv_bfloat16 (*As)[SKW],
                                          const __nv_bfloat16 (*Bs)[SKW],
                                          float c[2][8][4],
                                          int warp_m, int warp_n, int lane) {
    int g = lane >> 2, tig = lane & 3;
    #pragma unroll
    for (int ks = 0; ks < 4; ks++) {
        int k0 = ks * 16;
        uint32_t a[2][4], b[8][2];
        #pragma unroll
        for (int mt = 0; mt < 2; mt++) {
            int r = warp_m * 32 + mt * 16 + g;
            a[mt][0] = *(const uint32_t*)&As[r][k0 + tig * 2];
            a[mt][1] = *(const uint32_t*)&As[r + 8][k0 + tig * 2];
            a[mt][2] = *(const uint32_t*)&As[r][k0 + tig * 2 + 8];
            a[mt][3] = *(const uint32_t*)&As[r + 8][k0 + tig * 2 + 8];
        }
        #pragma unroll
        for (int nt = 0; nt < 8; nt++) {
            int n = warp_n * 64 + nt * 8 + g;
            b[nt][0] = *(const uint32_t*)&Bs[n][k0 + tig * 2];
            b[nt][1] = *(const uint32_t*)&Bs[n][k0 + tig * 2 + 8];
        }
        #pragma unroll
        for (int mt = 0; mt < 2; mt++)
            #pragma unroll
            for (int nt = 0; nt < 8; nt++)
                mma16816(c[mt][nt], a[mt], b[nt]);
    }
}

// ===================== L4: expand1 = ELU(aggx @ W1_h + b1) ==================
#define G1_SMEM (4 * CHUNK_B + 128 * 4)

__global__ __launch_bounds__(256) void expand1_kernel(const float* __restrict__ b1) {
    extern __shared__ char dsm[];
    __nv_bfloat16 (*Ab[2])[SKW] = {(__nv_bfloat16(*)[SKW])dsm,
                                   (__nv_bfloat16(*)[SKW])(dsm + 2 * CHUNK_B)};
    __nv_bfloat16 (*Bb[2])[SKW] = {(__nv_bfloat16(*)[SKW])(dsm + CHUNK_B),
                                   (__nv_bfloat16(*)[SKW])(dsm + 3 * CHUNK_B)};
    float* s_b = (float*)(dsm + 4 * CHUNK_B);

    int tid = threadIdx.x;
    int wid = tid >> 5, lane = tid & 31;
    int warp_m = wid & 3, warp_n = wid >> 2;
    int g = lane >> 2, tig = lane & 3;
    int h = blockIdx.x;
    int m0 = blockIdx.y * MT;

    if (tid < 128) s_b[tid] = b1[h * EMBED + tid];

    float c[2][8][4];
    #pragma unroll
    for (int mt = 0; mt < 2; mt++)
        #pragma unroll
        for (int nt = 0; nt < 8; nt++)
            #pragma unroll
            for (int i = 0; i < 4; i++) c[mt][nt][i] = 0.f;

    float4 pa[4], pb[4];
    fetch_chunk(g_axhi, HC, m0, h * EMBED, pa, tid);
    fetch_chunk(g_w1t_hi, EMBED, h * 128, 0, pb, tid);
    #pragma unroll
    for (int it = 0; it < 6; it++) {
        stash_chunk(pa, Ab[it & 1], tid);
        stash_chunk(pb, Bb[it & 1], tid);
        __syncthreads();
        if (it + 1 < 6) {
            int nx = it + 1;
            int p = nx >> 1, kc = (nx & 1) * 64;
            const __nv_bfloat16* Asrc = (p == 2) ? g_axlo : g_axhi;
            const __nv_bfloat16* Bsrc = (p == 1) ? g_w1t_lo : g_w1t_hi;
            fetch_chunk(Asrc, HC, m0, h * EMBED + kc, pa, tid);
            fetch_chunk(Bsrc, EMBED, h * 128, kc, pb, tid);
        }
        mma_chunk(Ab[it & 1], Bb[it & 1], c, warp_m, warp_n, lane);
        __syncthreads();
    }

    #pragma unroll
    for (int mt = 0; mt < 2; mt++) {
        int r = warp_m * 32 + mt * 16 + g;
        #pragma unroll
        for (int nt = 0; nt < 8; nt++) {
            int col = warp_n * 64 + nt * 8 + tig * 2;
            float* cc = c[mt][nt];
            #pragma unroll
            for (int q = 0; q < 2; q++) {
                float v0 = cc[q * 2 + 0] + s_b[col];
                float v1 = cc[q * 2 + 1] + s_b[col + 1];
                v0 = v0 > 0.f ? v0 : (__expf(v0) - 1.f);
                v1 = v1 > 0.f ? v1 : (__expf(v1) - 1.f);
                __nv_bfloat16 h0 = __float2bfloat16(v0);
                __nv_bfloat16 h1 = __float2bfloat16(v1);
                __nv_bfloat162 hh; hh.x = h0; hh.y = h1;
                __nv_bfloat162 ll;
                ll.x = __float2bfloat16(v0 - __bfloat162float(h0));
                ll.y = __float2bfloat16(v1 - __bfloat162float(h1));
                size_t base = (size_t)(m0 + r + q * 8) * HC + h * EMBED + col;
                *(__nv_bfloat162*)(g_x2hi + base) = hh;
                *(__nv_bfloat162*)(g_x2lo + base) = ll;
            }
        }
    }
}

// ===================== L5: GEMM2 K-split ====================================
#define G2_SMEM (4 * CHUNK_B)
#define G2_NIT  24

__global__ __launch_bounds__(256) void gemm2_kernel() {
    extern __shared__ char dsm[];
    __nv_bfloat16 (*Ab[2])[SKW] = {(__nv_bfloat16(*)[SKW])dsm,
                                   (__nv_bfloat16(*)[SKW])(dsm + 2 * CHUNK_B)};
    __nv_bfloat16 (*Bb[2])[SKW] = {(__nv_bfloat16(*)[SKW])(dsm + CHUNK_B),
                                   (__nv_bfloat16(*)[SKW])(dsm + 3 * CHUNK_B)};

    int tid = threadIdx.x;
    int wid = tid >> 5, lane = tid & 31;
    int warp_m = wid & 3, warp_n = wid >> 2;
    int g = lane >> 2, tig = lane & 3;
    int m0 = blockIdx.x * MT;
    int ks = blockIdx.y * 512;

    float c[2][8][4];
    #pragma unroll
    for (int mt = 0; mt < 2; mt++)
        #pragma unroll
        for (int nt = 0; nt < 8; nt++)
            #pragma unroll
            for (int i = 0; i < 4; i++) c[mt][nt][i] = 0.f;

    float4 pa[4], pb[4];
    fetch_chunk(g_x2hi, HC, m0, ks, pa, tid);
    fetch_chunk(g_w2t_hi, HC, 0, ks, pb, tid);
    for (int it = 0; it < G2_NIT; it++) {
        stash_chunk(pa, Ab[it & 1], tid);
        stash_chunk(pb, Bb[it & 1], tid);
        __syncthreads();
        if (it + 1 < G2_NIT) {
            int nx = it + 1;
            int p = nx >> 3, kc = ks + (nx & 7) * 64;
            const __nv_bfloat16* Asrc = (p == 2) ? g_x2lo : g_x2hi;
            const __nv_bfloat16* Bsrc = (p == 1) ? g_w2t_lo : g_w2t_hi;
            fetch_chunk(Asrc, HC, m0, kc, pa, tid);
            fetch_chunk(Bsrc, HC, 0, kc, pb, tid);
        }
        mma_chunk(Ab[it & 1], Bb[it & 1], c, warp_m, warp_n, lane);
        __syncthreads();
    }

    float* outp = g_h2p + (size_t)blockIdx.y * MPAD * EMBED;
    #pragma unroll
    for (int mt = 0; mt < 2; mt++) {
        int r = warp_m * 32 + mt * 16 + g;
        #pragma unroll
        for (int nt = 0; nt < 8; nt++) {
            int col = warp_n * 64 + nt * 8 + tig * 2;
            float* cc = c[mt][nt];
            size_t base = (size_t)(m0 + r) * EMBED + col;
            *(float2*)(outp + base) = make_float2(cc[0], cc[1]);
            *(float2*)(outp + base + 8 * EMBED) = make_float2(cc[2], cc[3]);
        }
    }
}

// ===================== L6: combine + al2 ====================================
__global__ void combine_kernel(const float* __restrict__ as2,
                               const float* __restrict__ ad2, int n) {
    int t = threadIdx.x;
    int row = blockIdx.x * 2 + (t >> 7);
    int col = t & 127;
    if (row >= n) return;
    size_t idx = (size_t)row * EMBED + col;
    float s = g_h2p[idx] + g_h2p[idx + (size_t)MPAD * EMBED]
            + g_h2p[idx + 2 * (size_t)MPAD * EMBED]
            + g_h2p[idx + 3 * (size_t)MPAD * EMBED];
    g_h2[idx] = __float2half(s);
    float a = s * __ldg(&as2[col]);
    float d = s * __ldg(&ad2[col]);
    #pragma unroll
    for (int o = 16; o > 0; o >>= 1) {
        a += __shfl_down_sync(0xffffffffu, a, o);
        d += __shfl_down_sync(0xffffffffu, d, o);
    }
    __shared__ float wa[8], wd[8];
    int w = t >> 5;
    if ((t & 31) == 0) { wa[w] = a; wd[w] = d; }
    __syncthreads();
    if ((t & 127) == 0) {
        int wb = (t >> 7) * 4;
        g_als2[row] = wa[wb] + wa[wb + 1] + wa[wb + 2] + wa[wb + 3];
        g_ald2[row] = wd[wb] + wd[wb + 1] + wd[wb + 2] + wd[wb + 3];
    }
}

// ===================== L7: agg2 + classifier, 2-phase =======================
__global__ void agg2cls_kernel(const float* __restrict__ b2,
                               const float* __restrict__ Wc,
                               const float* __restrict__ bc,
                               float* __restrict__ out) {
    int nno = blockIdx.x;
    int t = threadIdx.x;               // 128
    int beg = g_rowptr[nno];
    int deg = g_rowptr[nno + 1] - beg;
    float ad = g_ald2[nno];

    float lm = M_SENT, ls = 0.f;
    for (int j = t; j < deg; j += 128) {
        int src = __ldg(&g_col[beg + j]);
        float lg = __ldg(&g_als2[src]) + ad;
        lg = lg > 0.f ? lg : NEG_SLOPE * lg;
        if (lg > lm) { ls = ls * __expf(lm - lg) + 1.f; lm = lg; }
        else ls += __expf(lg - lm);
    }
    #pragma unroll
    for (int o = 16; o > 0; o >>= 1) {
        float om = __shfl_xor_sync(0xffffffffu, lm, o);
        float os = __shfl_xor_sync(0xffffffffu, ls, o);
        float nm = fmaxf(lm, om);
        ls = ls * __expf(lm - nm) + os * __expf(om - nm);
        lm = nm;
    }
    __shared__ float sm[4], ssum[4];
    if ((t & 31) == 0) { sm[t >> 5] = lm; ssum[t >> 5] = ls; }
    __syncthreads();
    float m = fmaxf(fmaxf(sm[0], sm[1]), fmaxf(sm[2], sm[3]));
    float s = ssum[0] * __expf(sm[0] - m) + ssum[1] * __expf(sm[1] - m)
            + ssum[2] * __expf(sm[2] - m) + ssum[3] * __expf(sm[3] - m);
    float inv = 1.f / (s + 1e-16f);

    float acc = 0.f;
    for (int j = 0; j < deg; j++) {
        int src = __ldg(&g_col[beg + j]);
        float lg = __ldg(&g_als2[src]) + ad;
        lg = lg > 0.f ? lg : NEG_SLOPE * lg;
        float w = __expf(lg - m) * inv;
        acc += w * __half2float(__ldg(&g_h2[(size_t)src * EMBED + t]));
    }
    float val = acc + b2[t];
    float part = val * __ldg(&Wc[t]);
    #pragma unroll
    for (int o = 16; o > 0; o >>= 1) part += __shfl_down_sync(0xffffffffu, part, o);
    __shared__ float ws[4];
    if ((t & 31) == 0) ws[t >> 5] = part;
    __syncthreads();
    if (t == 0) out[nno] = ws[0] + ws[1] + ws[2] + ws[3] + bc[0];
}

// ===================== launch ===============================================
extern "C" void kernel_launch(void* const* d_in, const int* in_sizes, int n_in,
                              void* d_out, int out_size) {
    const float* x   = (const float*)d_in[0];
    const void*  ei  = d_in[1];
    const float* W1  = (const float*)d_in[2];
    const float* as1 = (const float*)d_in[3];
    const float* ad1 = (const float*)d_in[4];
    const float* b1  = (const float*)d_in[5];
    const float* W2  = (const float*)d_in[6];
    const float* as2 = (const float*)d_in[7];
    const float* ad2 = (const float*)d_in[8];
    const float* b2  = (const float*)d_in[9];
    const float* Wc  = (const float*)d_in[10];
    const float* bc  = (const float*)d_in[11];
    float* out = (float*)d_out;

    int E = in_sizes[1] / 2;
    int n = in_sizes[0] / EMBED;
    int mtiles = (n + MT - 1) / MT;

    cudaFuncSetAttribute(expand1_kernel, cudaFuncAttributeMaxDynamicSharedMemorySize, G1_SMEM);
    cudaFuncSetAttribute(gemm2_kernel, cudaFuncAttributeMaxDynamicSharedMemorySize, G2_SMEM);

    int decode_blocks = (2 * E + 255) / 256;
    prep_decode_kernel<<<NB_PRE + decode_blocks, 256>>>(W1, W2, as1, ad1, ei, E); // 0
    scan_logits_kernel<<<1 + (n + 31) / 32, 1024>>>(x, n);                        // 1
    fill_kernel<<<(E + n + 255) / 256, 256>>>(E, n);                              // 2
    agg1_kernel<<<n, 128>>>(x);                                                   // 3 <- profiled
    expand1_kernel<<<dim3(HEADS, mtiles), 256, G1_SMEM>>>(b1);                    // 4
    gemm2_kernel<<<dim3(mtiles, KSPLIT), 256, G2_SMEM>>>();                       // 5
    combine_kernel<<<(n + 1) / 2, 256>>>(as2, ad2, n);                            // 6
    agg2cls_kernel<<<n, 128>>>(b2, Wc, bc, out);                                  // 7
}

// round 10
// speedup vs baseline: 1.2607x; 1.0530x over previous
#include <cuda_runtime.h>
#include <cuda_bf16.h>
#include <cuda_fp16.h>
#include <cstdint>

#define N_NODES 10000
#define EDGES   160000
#define EMBED   128
#define HEADS   16
#define HC      2048
#define NEG_SLOPE 0.2f
#define M_SENT  (-1e30f)
#define MT      128
#define MPAD    (79 * 128)
#define KSPLIT  8

// ===================== device scratch =======================================
__device__ int   g_src[EDGES];
__device__ int   g_dst[EDGES];
__device__ int   g_deg[N_NODES];          // zero-init; re-zeroed by fill each call
__device__ int   g_rowptr[N_NODES + 1];
__device__ int   g_cursor[N_NODES];
__device__ int   g_col[EDGES + N_NODES];

__device__ float g_waS[HEADS * EMBED];
__device__ float g_waD[HEADS * EMBED];
__device__ __nv_bfloat16 g_w1t_hi[(size_t)HC * EMBED];
__device__ __nv_bfloat16 g_w1t_lo[(size_t)HC * EMBED];
__device__ __nv_bfloat16 g_w2t_hi[(size_t)EMBED * HC];
__device__ __nv_bfloat16 g_w2t_lo[(size_t)EMBED * HC];
__device__ float g_als1[MPAD * HEADS];
__device__ float g_ald1[MPAD * HEADS];
__device__ __nv_bfloat16 g_axhi[(size_t)MPAD * HC];
__device__ __nv_bfloat16 g_axlo[(size_t)MPAD * HC];
__device__ __nv_bfloat16 g_x2hi[(size_t)MPAD * HC];
__device__ __nv_bfloat16 g_x2lo[(size_t)MPAD * HC];
__device__ float g_h2p[(size_t)KSPLIT * MPAD * EMBED];
__device__ __half g_h2[(size_t)MPAD * EMBED];
__device__ float g_als2[MPAD];
__device__ float g_ald2[MPAD];

// ===================== L0: prep + decode + count ============================
template <int R, int C>
__device__ void transpose_cv(const float* __restrict__ src,
                             __nv_bfloat16* __restrict__ dhi,
                             __nv_bfloat16* __restrict__ dlo, int bx, int by) {
    __shared__ float tile[32][33];
    int tx = threadIdx.x & 31, ty0 = threadIdx.x >> 5;
    #pragma unroll
    for (int j = 0; j < 4; j++) {
        int r = by * 32 + ty0 + j * 8, c = bx * 32 + tx;
        tile[ty0 + j * 8][tx] = src[(size_t)r * C + c];
    }
    __syncthreads();
    #pragma unroll
    for (int j = 0; j < 4; j++) {
        int rd = bx * 32 + ty0 + j * 8;
        int cd = by * 32 + tx;
        float v = tile[tx][ty0 + j * 8];
        __nv_bfloat16 h = __float2bfloat16(v);
        dhi[(size_t)rd * R + cd] = h;
        dlo[(size_t)rd * R + cd] = __float2bfloat16(v - __bfloat162float(h));
    }
}

#define NB_WA  16
#define NB_W1  256
#define NB_W2  256
#define NB_PRE (NB_WA + NB_W1 + NB_W2)

__global__ void prep_decode_kernel(const float* __restrict__ W1,
                                   const float* __restrict__ W2,
                                   const float* __restrict__ as1,
                                   const float* __restrict__ ad1,
                                   const void* __restrict__ ei, int E) {
    int b = blockIdx.x, t = threadIdx.x;
    if (b < NB_WA) {
        __shared__ float sa[EMBED], sd[EMBED];
        int h = b;
        if (t < 128) { sa[t] = as1[h * EMBED + t]; sd[t] = ad1[h * EMBED + t]; }
        __syncthreads();
        if (t < 128) {
            float ss = 0.f, ssd = 0.f;
            const float* wrow = W1 + (size_t)t * HC + h * EMBED;
            #pragma unroll 4
            for (int c = 0; c < EMBED; c++) {
                float w = wrow[c];
                ss += w * sa[c];
                ssd += w * sd[c];
            }
            g_waS[h * EMBED + t] = ss;
            g_waD[h * EMBED + t] = ssd;
        }
        return;
    }
    b -= NB_WA;
    if (b < NB_W1) { transpose_cv<128, 2048>(W1, g_w1t_hi, g_w1t_lo, b & 63, b >> 6); return; }
    b -= NB_W1;
    if (b < NB_W2) { transpose_cv<2048, 128>(W2, g_w2t_hi, g_w2t_lo, b & 3, b >> 2); return; }
    b -= NB_W2;
    const long long* p64 = (const long long*)ei;
    long long pv = p64[t];
    int ok = (pv >= 0 && pv < N_NODES);
    int is64 = __syncthreads_and(ok);
    int i = b * 256 + t;
    if (i >= 2 * E) return;
    int vi = is64 ? (int)p64[i] : ((const int*)ei)[i];
    if (i < E) g_src[i] = vi;
    else { g_dst[i - E] = vi; atomicAdd(&g_deg[vi], 1); }
}

// ===================== L1: scan (block 0) + logits1 =========================
__global__ void scan_logits_kernel(const float* __restrict__ x, int n) {
    int t = threadIdx.x;
    if (blockIdx.x == 0) {
        __shared__ int wsum[32];
        int CH = (n + 1023) / 1024;
        int base = t * CH;
        int s = 0;
        for (int k = 0; k < CH; k++) { int idx = base + k; if (idx < n) s += g_deg[idx] + 1; }
        int lane = t & 31, wid = t >> 5;
        int v = s;
        #pragma unroll
        for (int o = 1; o < 32; o <<= 1) {
            int t2 = __shfl_up_sync(0xffffffffu, v, o);
            if (lane >= o) v += t2;
        }
        if (lane == 31) wsum[wid] = v;
        __syncthreads();
        if (wid == 0) {
            int w = wsum[lane];
            #pragma unroll
            for (int o = 1; o < 32; o <<= 1) {
                int t2 = __shfl_up_sync(0xffffffffu, w, o);
                if (lane >= o) w += t2;
            }
            wsum[lane] = w;
        }
        __syncthreads();
        int excl = v - s + (wid ? wsum[wid - 1] : 0);
        int running = excl;
        for (int k = 0; k < CH; k++) {
            int idx = base + k;
            if (idx < n) {
                g_rowptr[idx] = running;
                g_cursor[idx] = running;
                running += g_deg[idx] + 1;
            }
        }
        if (t == 0) g_rowptr[n] = wsum[31];
        return;
    }
    int node = (blockIdx.x - 1) * 32 + (t >> 5);
    if (node >= n) return;
    int lane = t & 31;
    float4 xv = ((const float4*)(x + (size_t)node * EMBED))[lane];
    #pragma unroll
    for (int h = 0; h < HEADS; h++) {
        float4 wS = ((const float4*)(g_waS + h * EMBED))[lane];
        float4 wD = ((const float4*)(g_waD + h * EMBED))[lane];
        float ss = xv.x * wS.x + xv.y * wS.y + xv.z * wS.z + xv.w * wS.w;
        float sd = xv.x * wD.x + xv.y * wD.y + xv.z * wD.z + xv.w * wD.w;
        #pragma unroll
        for (int o = 16; o > 0; o >>= 1) {
            ss += __shfl_xor_sync(0xffffffffu, ss, o);
            sd += __shfl_xor_sync(0xffffffffu, sd, o);
        }
        if (lane == 0) {
            g_als1[node * HEADS + h] = ss;
            g_ald1[node * HEADS + h] = sd;
        }
    }
}

// ===================== L2: fill (+ deg self-clean) ==========================
__global__ void fill_kernel(int E, int n) {
    int i = blockIdx.x * blockDim.x + threadIdx.x;
    if (i < E) {
        int d = g_dst[i];
        int pos = atomicAdd(&g_cursor[d], 1);
        g_col[pos] = g_src[i];
    } else if (i < E + n) {
        int v = i - E;
        int pos = atomicAdd(&g_cursor[v], 1);
        g_col[pos] = v;
        g_deg[v] = 0;
    }
}

// ===================== L3 (PROFILED): agg1, head-shared gather ==============
#define ETILE 64

__global__ __launch_bounds__(128) void agg1_kernel(const float* __restrict__ x) {
    int nno = blockIdx.x;
    int t = threadIdx.x;               // 128 threads; phase2: t = channel
    int beg = g_rowptr[nno];
    int deg = g_rowptr[nno + 1] - beg;
    int h = t & 15, sub = t >> 4;      // phase1 roles

    __shared__ float s_ad[16], s_m[16], s_inv[16];
    __shared__ float s_pm[4][16], s_ps[4][16];
    __shared__ int   s_src[ETILE];
    __shared__ float sw[ETILE][16];

    if (t < 16) s_ad[t] = g_ald1[nno * HEADS + t];
    __syncthreads();

    // phase 1: per-head (m, s), 8-way edge parallel
    float ad = s_ad[h];
    float lm = M_SENT, ls = 0.f;
    for (int j = sub; j < deg; j += 8) {
        int src = __ldg(&g_col[beg + j]);
        float lg = __ldg(&g_als1[src * HEADS + h]) + ad;
        lg = lg > 0.f ? lg : NEG_SLOPE * lg;
        if (lg > lm) { ls = ls * __expf(lm - lg) + 1.f; lm = lg; }
        else ls += __expf(lg - lm);
    }
    {
        float om = __shfl_xor_sync(0xffffffffu, lm, 16);
        float os = __shfl_xor_sync(0xffffffffu, ls, 16);
        float nm = fmaxf(lm, om);
        ls = ls * __expf(lm - nm) + os * __expf(om - nm);
        lm = nm;
    }
    int warp = t >> 5;
    if ((t & 31) < 16) { s_pm[warp][h] = lm; s_ps[warp][h] = ls; }
    __syncthreads();
    if (t < 16) {
        float m0 = s_pm[0][t], m1 = s_pm[1][t], m2 = s_pm[2][t], m3 = s_pm[3][t];
        float mm = fmaxf(fmaxf(m0, m1), fmaxf(m2, m3));
        float ss = s_ps[0][t] * __expf(m0 - mm) + s_ps[1][t] * __expf(m1 - mm)
                 + s_ps[2][t] * __expf(m2 - mm) + s_ps[3][t] * __expf(m3 - mm);
        s_m[t] = mm;
        s_inv[t] = 1.f / (ss + 1e-16f);
    }
    __syncthreads();

    // phase 2: tiles of 64 edges; weights staged in shared, x loaded once/edge
    float acc[16];
    #pragma unroll
    for (int i = 0; i < 16; i++) acc[i] = 0.f;

    for (int e0 = 0; e0 < deg; e0 += ETILE) {
        int ne = min(ETILE, deg - e0);
        if (t < ne) s_src[t] = __ldg(&g_col[beg + e0 + t]);
        __syncthreads();
        for (int k = t; k < ne * 16; k += 128) {
            int e = k >> 4, hh = k & 15;
            int src = s_src[e];
            float lg = __ldg(&g_als1[src * HEADS + hh]) + s_ad[hh];
            lg = lg > 0.f ? lg : NEG_SLOPE * lg;
            sw[e][hh] = __expf(lg - s_m[hh]) * s_inv[hh];
        }
        __syncthreads();
        for (int e = 0; e < ne; e++) {
            float xv = __ldg(&x[(size_t)s_src[e] * EMBED + t]);
            float4 w0 = *(float4*)&sw[e][0];
            float4 w1 = *(float4*)&sw[e][4];
            float4 w2 = *(float4*)&sw[e][8];
            float4 w3 = *(float4*)&sw[e][12];
            acc[0]  += w0.x * xv;  acc[1]  += w0.y * xv;
            acc[2]  += w0.z * xv;  acc[3]  += w0.w * xv;
            acc[4]  += w1.x * xv;  acc[5]  += w1.y * xv;
            acc[6]  += w1.z * xv;  acc[7]  += w1.w * xv;
            acc[8]  += w2.x * xv;  acc[9]  += w2.y * xv;
            acc[10] += w2.z * xv;  acc[11] += w2.w * xv;
            acc[12] += w3.x * xv;  acc[13] += w3.y * xv;
            acc[14] += w3.z * xv;  acc[15] += w3.w * xv;
        }
        __syncthreads();
    }

    #pragma unroll
    for (int i = 0; i < 16; i++) {
        float v = acc[i];
        __nv_bfloat16 hi = __float2bfloat16(v);
        __nv_bfloat16 lo = __float2bfloat16(v - __bfloat162float(hi));
        g_axhi[(size_t)nno * HC + i * EMBED + t] = hi;
        g_axlo[(size_t)nno * HC + i * EMBED + t] = lo;
    }
}

// ===================== mma.sync GEMM machinery ==============================
#define SKW 72
#define CHUNK_B (128 * SKW * 2)

__device__ __forceinline__ void mma16816(float* c, const uint32_t* a, const uint32_t* b) {
    asm volatile("mma.sync.aligned.m16n8k16.row.col.f32.bf16.bf16.f32 "
        "{%0,%1,%2,%3}, {%4,%5,%6,%7}, {%8,%9}, {%0,%1,%2,%3};"
        : "+f"(c[0]), "+f"(c[1]), "+f"(c[2]), "+f"(c[3])
        : "r"(a[0]), "r"(a[1]), "r"(a[2]), "r"(a[3]), "r"(b[0]), "r"(b[1]));
}

__device__ __forceinline__ void fetch_chunk(const __nv_bfloat16* __restrict__ src,
                                            int ld, int row0, int k0,
                                            float4* r, int tid) {
    #pragma unroll
    for (int i = 0; i < 4; i++) {
        int c = tid + i * 256;
        int row = c >> 3;
        int kk = (c & 7) * 8;
        r[i] = *(const float4*)(src + (size_t)(row0 + row) * ld + k0 + kk);
    }
}

__device__ __forceinline__ void stash_chunk(const float4* r,
                                            __nv_bfloat16 (*S)[SKW], int tid) {
    #pragma unroll
    for (int i = 0; i < 4; i++) {
        int c = tid + i * 256;
        int row = c >> 3;
        int kk = (c & 7) * 8;
        *(float4*)&S[row][kk] = r[i];
    }
}

__device__ __forceinline__ void mma_chunk(const __nv_bfloat16 (*As)[SKW],
                                          const __nv_bfloat16 (*Bs)[SKW],
                                          float c[2][8][4],
                                          int warp_m, int warp_n, int lane) {
    int g = lane >> 2, tig = lane & 3;
    #pragma unroll
    for (int ks = 0; ks < 4; ks++) {
        int k0 = ks * 16;
        uint32_t a[2][4], b[8][2];
        #pragma unroll
        for (int mt = 0; mt < 2; mt++) {
            int r = warp_m * 32 + mt * 16 + g;
            a[mt][0] = *(const uint32_t*)&As[r][k0 + tig * 2];
            a[mt][1] = *(const uint32_t*)&As[r + 8][k0 + tig * 2];
            a[mt][2] = *(const uint32_t*)&As[r][k0 + tig * 2 + 8];
            a[mt][3] = *(const uint32_t*)&As[r + 8][k0 + tig * 2 + 8];
        }
        #pragma unroll
        for (int nt = 0; nt < 8; nt++) {
            int n = warp_n * 64 + nt * 8 + g;
            b[nt][0] = *(const uint32_t*)&Bs[n][k0 + tig * 2];
            b[nt][1] = *(const uint32_t*)&Bs[n][k0 + tig * 2 + 8];
        }
        #pragma unroll
        for (int mt = 0; mt < 2; mt++)
            #pragma unroll
            for (int nt = 0; nt < 8; nt++)
                mma16816(c[mt][nt], a[mt], b[nt]);
    }
}

// ===================== L4: expand1 = ELU(aggx @ W1_h + b1) ==================
#define G1_SMEM (4 * CHUNK_B + 128 * 4)

__global__ __launch_bounds__(256) void expand1_kernel(const float* __restrict__ b1) {
    extern __shared__ char dsm[];
    __nv_bfloat16 (*Ab[2])[SKW] = {(__nv_bfloat16(*)[SKW])dsm,
                                   (__nv_bfloat16(*)[SKW])(dsm + 2 * CHUNK_B)};
    __nv_bfloat16 (*Bb[2])[SKW] = {(__nv_bfloat16(*)[SKW])(dsm + CHUNK_B),
                                   (__nv_bfloat16(*)[SKW])(dsm + 3 * CHUNK_B)};
    float* s_b = (float*)(dsm + 4 * CHUNK_B);

    int tid = threadIdx.x;
    int wid = tid >> 5, lane = tid & 31;
    int warp_m = wid & 3, warp_n = wid >> 2;
    int g = lane >> 2, tig = lane & 3;
    int h = blockIdx.x;
    int m0 = blockIdx.y * MT;

    if (tid < 128) s_b[tid] = b1[h * EMBED + tid];

    float c[2][8][4];
    #pragma unroll
    for (int mt = 0; mt < 2; mt++)
        #pragma unroll
        for (int nt = 0; nt < 8; nt++)
            #pragma unroll
            for (int i = 0; i < 4; i++) c[mt][nt][i] = 0.f;

    float4 pa[4], pb[4];
    fetch_chunk(g_axhi, HC, m0, h * EMBED, pa, tid);
    fetch_chunk(g_w1t_hi, EMBED, h * 128, 0, pb, tid);
    #pragma unroll
    for (int it = 0; it < 6; it++) {
        stash_chunk(pa, Ab[it & 1], tid);
        stash_chunk(pb, Bb[it & 1], tid);
        __syncthreads();
        if (it + 1 < 6) {
            int nx = it + 1;
            int p = nx >> 1, kc = (nx & 1) * 64;
            const __nv_bfloat16* Asrc = (p == 2) ? g_axlo : g_axhi;
            const __nv_bfloat16* Bsrc = (p == 1) ? g_w1t_lo : g_w1t_hi;
            fetch_chunk(Asrc, HC, m0, h * EMBED + kc, pa, tid);
            fetch_chunk(Bsrc, EMBED, h * 128, kc, pb, tid);
        }
        mma_chunk(Ab[it & 1], Bb[it & 1], c, warp_m, warp_n, lane);
        __syncthreads();
    }

    #pragma unroll
    for (int mt = 0; mt < 2; mt++) {
        int r = warp_m * 32 + mt * 16 + g;
        #pragma unroll
        for (int nt = 0; nt < 8; nt++) {
            int col = warp_n * 64 + nt * 8 + tig * 2;
            float* cc = c[mt][nt];
            #pragma unroll
            for (int q = 0; q < 2; q++) {
                float v0 = cc[q * 2 + 0] + s_b[col];
                float v1 = cc[q * 2 + 1] + s_b[col + 1];
                v0 = v0 > 0.f ? v0 : (__expf(v0) - 1.f);
                v1 = v1 > 0.f ? v1 : (__expf(v1) - 1.f);
                __nv_bfloat16 h0 = __float2bfloat16(v0);
                __nv_bfloat16 h1 = __float2bfloat16(v1);
                __nv_bfloat162 hh; hh.x = h0; hh.y = h1;
                __nv_bfloat162 ll;
                ll.x = __float2bfloat16(v0 - __bfloat162float(h0));
                ll.y = __float2bfloat16(v1 - __bfloat162float(h1));
                size_t base = (size_t)(m0 + r + q * 8) * HC + h * EMBED + col;
                *(__nv_bfloat162*)(g_x2hi + base) = hh;
                *(__nv_bfloat162*)(g_x2lo + base) = ll;
            }
        }
    }
}

// ===================== L5: GEMM2 K-split (8 splits of 256) ==================
#define G2_SMEM (4 * CHUNK_B)
#define G2_NIT  12   // 3 passes x 4 k-chunks (256 per split)

__global__ __launch_bounds__(256) void gemm2_kernel() {
    extern __shared__ char dsm[];
    __nv_bfloat16 (*Ab[2])[SKW] = {(__nv_bfloat16(*)[SKW])dsm,
                                   (__nv_bfloat16(*)[SKW])(dsm + 2 * CHUNK_B)};
    __nv_bfloat16 (*Bb[2])[SKW] = {(__nv_bfloat16(*)[SKW])(dsm + CHUNK_B),
                                   (__nv_bfloat16(*)[SKW])(dsm + 3 * CHUNK_B)};

    int tid = threadIdx.x;
    int wid = tid >> 5, lane = tid & 31;
    int warp_m = wid & 3, warp_n = wid >> 2;
    int g = lane >> 2, tig = lane & 3;
    int m0 = blockIdx.x * MT;
    int ks = blockIdx.y * 256;

    float c[2][8][4];
    #pragma unroll
    for (int mt = 0; mt < 2; mt++)
        #pragma unroll
        for (int nt = 0; nt < 8; nt++)
            #pragma unroll
            for (int i = 0; i < 4; i++) c[mt][nt][i] = 0.f;

    float4 pa[4], pb[4];
    fetch_chunk(g_x2hi, HC, m0, ks, pa, tid);
    fetch_chunk(g_w2t_hi, HC, 0, ks, pb, tid);
    for (int it = 0; it < G2_NIT; it++) {
        stash_chunk(pa, Ab[it & 1], tid);
        stash_chunk(pb, Bb[it & 1], tid);
        __syncthreads();
        if (it + 1 < G2_NIT) {
            int nx = it + 1;
            int p = nx >> 2, kc = ks + (nx & 3) * 64;
            const __nv_bfloat16* Asrc = (p == 2) ? g_x2lo : g_x2hi;
            const __nv_bfloat16* Bsrc = (p == 1) ? g_w2t_lo : g_w2t_hi;
            fetch_chunk(Asrc, HC, m0, kc, pa, tid);
            fetch_chunk(Bsrc, HC, 0, kc, pb, tid);
        }
        mma_chunk(Ab[it & 1], Bb[it & 1], c, warp_m, warp_n, lane);
        __syncthreads();
    }

    float* outp = g_h2p + (size_t)blockIdx.y * MPAD * EMBED;
    #pragma unroll
    for (int mt = 0; mt < 2; mt++) {
        int r = warp_m * 32 + mt * 16 + g;
        #pragma unroll
        for (int nt = 0; nt < 8; nt++) {
            int col = warp_n * 64 + nt * 8 + tig * 2;
            float* cc = c[mt][nt];
            size_t base = (size_t)(m0 + r) * EMBED + col;
            *(float2*)(outp + base) = make_float2(cc[0], cc[1]);
            *(float2*)(outp + base + 8 * EMBED) = make_float2(cc[2], cc[3]);
        }
    }
}

// ===================== L6: combine + al2 ====================================
__global__ void combine_kernel(const float* __restrict__ as2,
                               const float* __restrict__ ad2, int n) {
    int t = threadIdx.x;
    int row = blockIdx.x * 2 + (t >> 7);
    int col = t & 127;
    if (row >= n) return;
    size_t idx = (size_t)row * EMBED + col;
    float s = 0.f;
    #pragma unroll
    for (int k = 0; k < KSPLIT; k++)
        s += g_h2p[idx + (size_t)k * MPAD * EMBED];
    g_h2[idx] = __float2half(s);
    float a = s * __ldg(&as2[col]);
    float d = s * __ldg(&ad2[col]);
    #pragma unroll
    for (int o = 16; o > 0; o >>= 1) {
        a += __shfl_down_sync(0xffffffffu, a, o);
        d += __shfl_down_sync(0xffffffffu, d, o);
    }
    __shared__ float wa[8], wd[8];
    int w = t >> 5;
    if ((t & 31) == 0) { wa[w] = a; wd[w] = d; }
    __syncthreads();
    if ((t & 127) == 0) {
        int wb = (t >> 7) * 4;
        g_als2[row] = wa[wb] + wa[wb + 1] + wa[wb + 2] + wa[wb + 3];
        g_ald2[row] = wd[wb] + wd[wb + 1] + wd[wb + 2] + wd[wb + 3];
    }
}

// ===================== L7: agg2 + classifier, staged weights ================
__global__ void agg2cls_kernel(const float* __restrict__ b2,
                               const float* __restrict__ Wc,
                               const float* __restrict__ bc,
                               float* __restrict__ out) {
    int nno = blockIdx.x;
    int t = threadIdx.x;               // 128
    int beg = g_rowptr[nno];
    int deg = g_rowptr[nno + 1] - beg;
    float ad = g_ald2[nno];

    __shared__ int   s_src[ETILE];
    __shared__ float s_w[ETILE];

    // phase 1: (m, s) with 128-way edge parallel
    float lm = M_SENT, ls = 0.f;
    for (int j = t; j < deg; j += 128) {
        int src = __ldg(&g_col[beg + j]);
        float lg = __ldg(&g_als2[src]) + ad;
        lg = lg > 0.f ? lg : NEG_SLOPE * lg;
        if (lg > lm) { ls = ls * __expf(lm - lg) + 1.f; lm = lg; }
        else ls += __expf(lg - lm);
    }
    #pragma unroll
    for (int o = 16; o > 0; o >>= 1) {
        float om = __shfl_xor_sync(0xffffffffu, lm, o);
        float os = __shfl_xor_sync(0xffffffffu, ls, o);
        float nm = fmaxf(lm, om);
        ls = ls * __expf(lm - nm) + os * __expf(om - nm);
        lm = nm;
    }
    __shared__ float sm[4], ssum[4];
    if ((t & 31) == 0) { sm[t >> 5] = lm; ssum[t >> 5] = ls; }
    __syncthreads();
    float m = fmaxf(fmaxf(sm[0], sm[1]), fmaxf(sm[2], sm[3]));
    float s = ssum[0] * __expf(sm[0] - m) + ssum[1] * __expf(sm[1] - m)
            + ssum[2] * __expf(sm[2] - m) + ssum[3] * __expf(sm[3] - m);
    float inv = 1.f / (s + 1e-16f);

    // phase 2: staged weights, coalesced h2 gather
    float acc = 0.f;
    for (int e0 = 0; e0 < deg; e0 += ETILE) {
        int ne = min(ETILE, deg - e0);
        __syncthreads();
        if (t < ne) {
            int src = __ldg(&g_col[beg + e0 + t]);
            s_src[t] = src;
            float lg = __ldg(&g_als2[src]) + ad;
            lg = lg > 0.f ? lg : NEG_SLOPE * lg;
            s_w[t] = __expf(lg - m) * inv;
        }
        __syncthreads();
        for (int e = 0; e < ne; e++)
            acc += s_w[e] * __half2float(__ldg(&g_h2[(size_t)s_src[e] * EMBED + t]));
    }
    float val = acc + b2[t];
    float part = val * __ldg(&Wc[t]);
    #pragma unroll
    for (int o = 16; o > 0; o >>= 1) part += __shfl_down_sync(0xffffffffu, part, o);
    __shared__ float ws[4];
    if ((t & 31) == 0) ws[t >> 5] = part;
    __syncthreads();
    if (t == 0) out[nno] = ws[0] + ws[1] + ws[2] + ws[3] + bc[0];
}

// ===================== launch ===============================================
extern "C" void kernel_launch(void* const* d_in, const int* in_sizes, int n_in,
                              void* d_out, int out_size) {
    const float* x   = (const float*)d_in[0];
    const void*  ei  = d_in[1];
    const float* W1  = (const float*)d_in[2];
    const float* as1 = (const float*)d_in[3];
    const float* ad1 = (const float*)d_in[4];
    const float* b1  = (const float*)d_in[5];
    const float* W2  = (const float*)d_in[6];
    const float* as2 = (const float*)d_in[7];
    const float* ad2 = (const float*)d_in[8];
    const float* b2  = (const float*)d_in[9];
    const float* Wc  = (const float*)d_in[10];
    const float* bc  = (const float*)d_in[11];
    float* out = (float*)d_out;

    int E = in_sizes[1] / 2;
    int n = in_sizes[0] / EMBED;
    int mtiles = (n + MT - 1) / MT;

    cudaFuncSetAttribute(expand1_kernel, cudaFuncAttributeMaxDynamicSharedMemorySize, G1_SMEM);
    cudaFuncSetAttribute(gemm2_kernel, cudaFuncAttributeMaxDynamicSharedMemorySize, G2_SMEM);

    int decode_blocks = (2 * E + 255) / 256;
    prep_decode_kernel<<<NB_PRE + decode_blocks, 256>>>(W1, W2, as1, ad1, ei, E); // 0
    scan_logits_kernel<<<1 + (n + 31) / 32, 1024>>>(x, n);                        // 1
    fill_kernel<<<(E + n + 255) / 256, 256>>>(E, n);                              // 2
    agg1_kernel<<<n, 128>>>(x);                                                   // 3 <- profiled
    expand1_kernel<<<dim3(HEADS, mtiles), 256, G1_SMEM>>>(b1);                    // 4
    gemm2_kernel<<<dim3(mtiles, KSPLIT), 256, G2_SMEM>>>();                       // 5
    combine_kernel<<<(n + 1) / 2, 256>>>(as2, ad2, n);                            // 6
    agg2cls_kernel<<<n, 128>>>(b2, Wc, bc, out);                                  // 7
}

// round 12
// speedup vs baseline: 2.1073x; 1.6715x over previous
#include <cuda_runtime.h>
#include <cuda_bf16.h>
#include <cuda_fp16.h>
#include <cstdint>

#define N_NODES 10000
#define EDGES   160000
#define EMBED   128
#define HEADS   16
#define HC      2048
#define NEG_SLOPE 0.2f
#define M_SENT  (-1e30f)
#define MT      128
#define MPAD    (79 * 128)
#define KSPLIT  4
#define ETILE   64

// ===================== device scratch =======================================
__device__ int   g_src[EDGES];
__device__ int   g_dst[EDGES];
__device__ int   g_deg[N_NODES];          // zero-init; re-zeroed by fill each call
__device__ int   g_rowptr[N_NODES + 1];
__device__ int   g_cursor[N_NODES];
__device__ int   g_col[EDGES + N_NODES];

__device__ float g_waS[HEADS * EMBED];
__device__ float g_waD[HEADS * EMBED];
__device__ __half g_w1t[(size_t)HC * EMBED];     // [n=2048][k=128] fp16
__device__ __half g_w2t[(size_t)EMBED * HC];     // [n=128][k=2048] fp16
__device__ float g_als1[MPAD * HEADS];
__device__ float g_ald1[MPAD * HEADS];
__device__ __half g_ax[(size_t)MPAD * HC];       // aggregated x per head, fp16
__device__ __half g_x2[(size_t)MPAD * HC];       // fp16
__device__ float g_h2p[(size_t)KSPLIT * MPAD * EMBED];
__device__ __half g_h2[(size_t)MPAD * EMBED];
__device__ float g_als2[MPAD];
__device__ float g_ald2[MPAD];

// ===================== L0: prep + decode + count ============================
template <int R, int C>
__device__ void transpose_cv(const float* __restrict__ src,
                             __half* __restrict__ dst, int bx, int by) {
    __shared__ float tile[32][33];
    int tx = threadIdx.x & 31, ty0 = threadIdx.x >> 5;
    #pragma unroll
    for (int j = 0; j < 4; j++) {
        int r = by * 32 + ty0 + j * 8, c = bx * 32 + tx;
        tile[ty0 + j * 8][tx] = src[(size_t)r * C + c];
    }
    __syncthreads();
    #pragma unroll
    for (int j = 0; j < 4; j++) {
        int rd = bx * 32 + ty0 + j * 8;
        int cd = by * 32 + tx;
        dst[(size_t)rd * R + cd] = __float2half(tile[tx][ty0 + j * 8]);
    }
}

#define NB_WA  16
#define NB_W1  256
#define NB_W2  256
#define NB_PRE (NB_WA + NB_W1 + NB_W2)

__global__ void prep_decode_kernel(const float* __restrict__ W1,
                                   const float* __restrict__ W2,
                                   const float* __restrict__ as1,
                                   const float* __restrict__ ad1,
                                   const void* __restrict__ ei, int E) {
    int b = blockIdx.x, t = threadIdx.x;
    if (b < NB_WA) {
        __shared__ float sa[EMBED], sd[EMBED];
        int h = b;
        if (t < 128) { sa[t] = as1[h * EMBED + t]; sd[t] = ad1[h * EMBED + t]; }
        __syncthreads();
        if (t < 128) {
            float ss = 0.f, ssd = 0.f;
            const float* wrow = W1 + (size_t)t * HC + h * EMBED;
            #pragma unroll 4
            for (int c = 0; c < EMBED; c++) {
                float w = wrow[c];
                ss += w * sa[c];
                ssd += w * sd[c];
            }
            g_waS[h * EMBED + t] = ss;
            g_waD[h * EMBED + t] = ssd;
        }
        return;
    }
    b -= NB_WA;
    if (b < NB_W1) { transpose_cv<128, 2048>(W1, g_w1t, b & 63, b >> 6); return; }
    b -= NB_W1;
    if (b < NB_W2) { transpose_cv<2048, 128>(W2, g_w2t, b & 3, b >> 2); return; }
    b -= NB_W2;
    const long long* p64 = (const long long*)ei;
    long long pv = p64[t];
    int ok = (pv >= 0 && pv < N_NODES);
    int is64 = __syncthreads_and(ok);
    int i = b * 256 + t;
    if (i >= 2 * E) return;
    int vi = is64 ? (int)p64[i] : ((const int*)ei)[i];
    if (i < E) g_src[i] = vi;
    else { g_dst[i - E] = vi; atomicAdd(&g_deg[vi], 1); }
}

// ===================== L1: scan (block 0) + logits1 =========================
__global__ void scan_logits_kernel(const float* __restrict__ x, int n) {
    int t = threadIdx.x;
    if (blockIdx.x == 0) {
        __shared__ int wsum[32];
        int CH = (n + 1023) / 1024;
        int base = t * CH;
        int s = 0;
        for (int k = 0; k < CH; k++) { int idx = base + k; if (idx < n) s += g_deg[idx] + 1; }
        int lane = t & 31, wid = t >> 5;
        int v = s;
        #pragma unroll
        for (int o = 1; o < 32; o <<= 1) {
            int t2 = __shfl_up_sync(0xffffffffu, v, o);
            if (lane >= o) v += t2;
        }
        if (lane == 31) wsum[wid] = v;
        __syncthreads();
        if (wid == 0) {
            int w = wsum[lane];
            #pragma unroll
            for (int o = 1; o < 32; o <<= 1) {
                int t2 = __shfl_up_sync(0xffffffffu, w, o);
                if (lane >= o) w += t2;
            }
            wsum[lane] = w;
        }
        __syncthreads();
        int excl = v - s + (wid ? wsum[wid - 1] : 0);
        int running = excl;
        for (int k = 0; k < CH; k++) {
            int idx = base + k;
            if (idx < n) {
                g_rowptr[idx] = running;
                g_cursor[idx] = running;
                running += g_deg[idx] + 1;
            }
        }
        if (t == 0) g_rowptr[n] = wsum[31];
        return;
    }
    int node = (blockIdx.x - 1) * 32 + (t >> 5);
    if (node >= n) return;
    int lane = t & 31;
    float4 xv = ((const float4*)(x + (size_t)node * EMBED))[lane];
    #pragma unroll
    for (int h = 0; h < HEADS; h++) {
        float4 wS = ((const float4*)(g_waS + h * EMBED))[lane];
        float4 wD = ((const float4*)(g_waD + h * EMBED))[lane];
        float ss = xv.x * wS.x + xv.y * wS.y + xv.z * wS.z + xv.w * wS.w;
        float sd = xv.x * wD.x + xv.y * wD.y + xv.z * wD.z + xv.w * wD.w;
        #pragma unroll
        for (int o = 16; o > 0; o >>= 1) {
            ss += __shfl_xor_sync(0xffffffffu, ss, o);
            sd += __shfl_xor_sync(0xffffffffu, sd, o);
        }
        if (lane == 0) {
            g_als1[node * HEADS + h] = ss;
            g_ald1[node * HEADS + h] = sd;
        }
    }
}

// ===================== L2: fill (+ deg self-clean) ==========================
__global__ void fill_kernel(int E, int n) {
    int i = blockIdx.x * blockDim.x + threadIdx.x;
    if (i < E) {
        int d = g_dst[i];
        int pos = atomicAdd(&g_cursor[d], 1);
        g_col[pos] = g_src[i];
    } else if (i < E + n) {
        int v = i - E;
        int pos = atomicAdd(&g_cursor[v], 1);
        g_col[pos] = v;
        g_deg[v] = 0;
    }
}

// ===================== L3 (PROFILED): agg1, single-gather flash =============
__global__ __launch_bounds__(128) void agg1_kernel(const float* __restrict__ x) {
    int nno = blockIdx.x;
    int t = threadIdx.x;               // 128; phase2: t = channel
    int beg = g_rowptr[nno];
    int deg = g_rowptr[nno + 1] - beg;
    int h = t & 15, sub = t >> 4;
    int warp = t >> 5, lane = t & 31;

    __shared__ float s_ad[16], s_run_m[16], s_run_s[16], s_scale[16], s_inv[16];
    __shared__ float s_pm[4][16], s_ps[4][16];
    __shared__ int   s_src[ETILE];
    __shared__ float sw[ETILE][16];

    if (t < 16) {
        s_ad[t] = g_ald1[nno * HEADS + t];
        s_run_m[t] = M_SENT;
        s_run_s[t] = 0.f;
    }
    float acc[16];
    #pragma unroll
    for (int i = 0; i < 16; i++) acc[i] = 0.f;
    __syncthreads();

    for (int e0 = 0; e0 < deg; e0 += ETILE) {
        int ne = min(ETILE, deg - e0);
        if (t < ne) s_src[t] = __ldg(&g_col[beg + e0 + t]);
        __syncthreads();
        // single gather: raw leaky logits into sw
        for (int k = t; k < ne * 16; k += 128) {
            int e = k >> 4;                         // h == t&15 invariant
            float lg = __ldg(&g_als1[s_src[e] * HEADS + h]) + s_ad[h];
            sw[e][h] = lg > 0.f ? lg : NEG_SLOPE * lg;
        }
        __syncthreads();
        // tile max per head (pure fmax)
        float tm = M_SENT;
        for (int e = sub; e < ne; e += 8) tm = fmaxf(tm, sw[e][h]);
        tm = fmaxf(tm, __shfl_xor_sync(0xffffffffu, tm, 16));
        if (lane < 16) s_pm[warp][h] = tm;
        __syncthreads();
        if (t < 16) {
            float mt = fmaxf(fmaxf(s_pm[0][t], s_pm[1][t]), fmaxf(s_pm[2][t], s_pm[3][t]));
            float nm = fmaxf(s_run_m[t], mt);
            float sc = __expf(s_run_m[t] - nm);    // first tile: exp(-huge)=0
            s_scale[t] = sc;
            s_run_m[t] = nm;
            s_run_s[t] *= sc;
        }
        __syncthreads();
        // one exp per entry; partial sums per head
        float psum = 0.f;
        for (int k = t; k < ne * 16; k += 128) {
            int e = k >> 4;
            float w = __expf(sw[e][h] - s_run_m[h]);
            sw[e][h] = w;
            psum += w;
        }
        psum += __shfl_xor_sync(0xffffffffu, psum, 16);
        if (lane < 16) s_ps[warp][h] = psum;
        __syncthreads();
        if (t < 16)
            s_run_s[t] += s_ps[0][t] + s_ps[1][t] + s_ps[2][t] + s_ps[3][t];
        // rescale accumulators
        #pragma unroll
        for (int i = 0; i < 16; i++) acc[i] *= s_scale[i];
        // weighted accumulation: x loaded once per edge, coalesced
        for (int e = 0; e < ne; e++) {
            float xv = __ldg(&x[(size_t)s_src[e] * EMBED + t]);
            float4 w0 = *(float4*)&sw[e][0];
            float4 w1 = *(float4*)&sw[e][4];
            float4 w2 = *(float4*)&sw[e][8];
            float4 w3 = *(float4*)&sw[e][12];
            acc[0]  += w0.x * xv;  acc[1]  += w0.y * xv;
            acc[2]  += w0.z * xv;  acc[3]  += w0.w * xv;
            acc[4]  += w1.x * xv;  acc[5]  += w1.y * xv;
            acc[6]  += w1.z * xv;  acc[7]  += w1.w * xv;
            acc[8]  += w2.x * xv;  acc[9]  += w2.y * xv;
            acc[10] += w2.z * xv;  acc[11] += w2.w * xv;
            acc[12] += w3.x * xv;  acc[13] += w3.y * xv;
            acc[14] += w3.z * xv;  acc[15] += w3.w * xv;
        }
        __syncthreads();
    }
    if (t < 16) s_inv[t] = 1.f / (s_run_s[t] + 1e-16f);
    __syncthreads();
    #pragma unroll
    for (int i = 0; i < 16; i++)
        g_ax[(size_t)nno * HC + i * EMBED + t] = __float2half(acc[i] * s_inv[i]);
}

// ===================== mma.sync fp16 GEMM machinery =========================
#define SKW 72
#define CHUNK_B (128 * SKW * 2)

__device__ __forceinline__ void mma16816(float* c, const uint32_t* a, const uint32_t* b) {
    asm volatile("mma.sync.aligned.m16n8k16.row.col.f32.f16.f16.f32 "
        "{%0,%1,%2,%3}, {%4,%5,%6,%7}, {%8,%9}, {%0,%1,%2,%3};"
        : "+f"(c[0]), "+f"(c[1]), "+f"(c[2]), "+f"(c[3])
        : "r"(a[0]), "r"(a[1]), "r"(a[2]), "r"(a[3]), "r"(b[0]), "r"(b[1]));
}

__device__ __forceinline__ void fetch_chunk(const __half* __restrict__ src,
                                            int ld, int row0, int k0,
                                            float4* r, int tid) {
    #pragma unroll
    for (int i = 0; i < 4; i++) {
        int c = tid + i * 256;
        int row = c >> 3;
        int kk = (c & 7) * 8;
        r[i] = *(const float4*)(src + (size_t)(row0 + row) * ld + k0 + kk);
    }
}

__device__ __forceinline__ void stash_chunk(const float4* r,
                                            __half (*S)[SKW], int tid) {
    #pragma unroll
    for (int i = 0; i < 4; i++) {
        int c = tid + i * 256;
        int row = c >> 3;
        int kk = (c & 7) * 8;
        *(float4*)&S[row][kk] = r[i];
    }
}

__device__ __forceinline__ void mma_chunk(const __half (*As)[SKW],
                                          const __half (*Bs)[SKW],
                                          float c[2][8][4],
                                          int warp_m, int warp_n, int lane) {
    int g = lane >> 2, tig = lane & 3;
    #pragma unroll
    for (int ks = 0; ks < 4; ks++) {
        int k0 = ks * 16;
        uint32_t a[2][4], b[8][2];
        #pragma unroll
        for (int mt = 0; mt < 2; mt++) {
            int r = warp_m * 32 + mt * 16 + g;
            a[mt][0] = *(const uint32_t*)&As[r][k0 + tig * 2];
            a[mt][1] = *(const uint32_t*)&As[r + 8][k0 + tig * 2];
            a[mt][2] = *(const uint32_t*)&As[r][k0 + tig * 2 + 8];
            a[mt][3] = *(const uint32_t*)&As[r + 8][k0 + tig * 2 + 8];
        }
        #pragma unroll
        for (int nt = 0; nt < 8; nt++) {
            int n = warp_n * 64 + nt * 8 + g;
            b[nt][0] = *(const uint32_t*)&Bs[n][k0 + tig * 2];
            b[nt][1] = *(const uint32_t*)&Bs[n][k0 + tig * 2 + 8];
        }
        #pragma unroll
        for (int mt = 0; mt < 2; mt++)
            #pragma unroll
            for (int nt = 0; nt < 8; nt++)
                mma16816(c[mt][nt], a[mt], b[nt]);
    }
}

// ===================== L4: expand1 = ELU(aggx @ W1_h + b1), 1 pass ==========
#define G1_SMEM (4 * CHUNK_B + 128 * 4)

__global__ __launch_bounds__(256) void expand1_kernel(const float* __restrict__ b1) {
    extern __shared__ char dsm[];
    __half (*Ab[2])[SKW] = {(__half(*)[SKW])dsm, (__half(*)[SKW])(dsm + 2 * CHUNK_B)};
    __half (*Bb[2])[SKW] = {(__half(*)[SKW])(dsm + CHUNK_B),
                            (__half(*)[SKW])(dsm + 3 * CHUNK_B)};
    float* s_b = (float*)(dsm + 4 * CHUNK_B);

    int tid = threadIdx.x;
    int wid = tid >> 5, lane = tid & 31;
    int warp_m = wid & 3, warp_n = wid >> 2;
    int g = lane >> 2, tig = lane & 3;
    int h = blockIdx.x;
    int m0 = blockIdx.y * MT;

    if (tid < 128) s_b[tid] = b1[h * EMBED + tid];

    float c[2][8][4];
    #pragma unroll
    for (int mt = 0; mt < 2; mt++)
        #pragma unroll
        for (int nt = 0; nt < 8; nt++)
            #pragma unroll
            for (int i = 0; i < 4; i++) c[mt][nt][i] = 0.f;

    float4 pa[4], pb[4];
    fetch_chunk(g_ax, HC, m0, h * EMBED, pa, tid);
    fetch_chunk(g_w1t, EMBED, h * 128, 0, pb, tid);
    #pragma unroll
    for (int it = 0; it < 2; it++) {
        stash_chunk(pa, Ab[it & 1], tid);
        stash_chunk(pb, Bb[it & 1], tid);
        __syncthreads();
        if (it == 0) {
            fetch_chunk(g_ax, HC, m0, h * EMBED + 64, pa, tid);
            fetch_chunk(g_w1t, EMBED, h * 128, 64, pb, tid);
        }
        mma_chunk(Ab[it & 1], Bb[it & 1], c, warp_m, warp_n, lane);
        __syncthreads();
    }

    #pragma unroll
    for (int mt = 0; mt < 2; mt++) {
        int r = warp_m * 32 + mt * 16 + g;
        #pragma unroll
        for (int nt = 0; nt < 8; nt++) {
            int col = warp_n * 64 + nt * 8 + tig * 2;
            float* cc = c[mt][nt];
            #pragma unroll
            for (int q = 0; q < 2; q++) {
                float v0 = cc[q * 2 + 0] + s_b[col];
                float v1 = cc[q * 2 + 1] + s_b[col + 1];
                v0 = v0 > 0.f ? v0 : (__expf(v0) - 1.f);
                v1 = v1 > 0.f ? v1 : (__expf(v1) - 1.f);
                size_t base = (size_t)(m0 + r + q * 8) * HC + h * EMBED + col;
                *(__half2*)(g_x2 + base) = __floats2half2_rn(v0, v1);
            }
        }
    }
}

// ===================== L5: GEMM2 K-split (4 splits of 512), 1 pass ==========
#define G2_SMEM (4 * CHUNK_B)
#define G2_NIT  8

__global__ __launch_bounds__(256) void gemm2_kernel() {
    extern __shared__ char dsm[];
    __half (*Ab[2])[SKW] = {(__half(*)[SKW])dsm, (__half(*)[SKW])(dsm + 2 * CHUNK_B)};
    __half (*Bb[2])[SKW] = {(__half(*)[SKW])(dsm + CHUNK_B),
                            (__half(*)[SKW])(dsm + 3 * CHUNK_B)};

    int tid = threadIdx.x;
    int wid = tid >> 5, lane = tid & 31;
    int warp_m = wid & 3, warp_n = wid >> 2;
    int g = lane >> 2, tig = lane & 3;
    int m0 = blockIdx.x * MT;
    int ks = blockIdx.y * 512;

    float c[2][8][4];
    #pragma unroll
    for (int mt = 0; mt < 2; mt++)
        #pragma unroll
        for (int nt = 0; nt < 8; nt++)
            #pragma unroll
            for (int i = 0; i < 4; i++) c[mt][nt][i] = 0.f;

    float4 pa[4], pb[4];
    fetch_chunk(g_x2, HC, m0, ks, pa, tid);
    fetch_chunk(g_w2t, HC, 0, ks, pb, tid);
    for (int it = 0; it < G2_NIT; it++) {
        stash_chunk(pa, Ab[it & 1], tid);
        stash_chunk(pb, Bb[it & 1], tid);
        __syncthreads();
        if (it + 1 < G2_NIT) {
            int kc = ks + (it + 1) * 64;
            fetch_chunk(g_x2, HC, m0, kc, pa, tid);
            fetch_chunk(g_w2t, HC, 0, kc, pb, tid);
        }
        mma_chunk(Ab[it & 1], Bb[it & 1], c, warp_m, warp_n, lane);
        __syncthreads();
    }

    float* outp = g_h2p + (size_t)blockIdx.y * MPAD * EMBED;
    #pragma unroll
    for (int mt = 0; mt < 2; mt++) {
        int r = warp_m * 32 + mt * 16 + g;
        #pragma unroll
        for (int nt = 0; nt < 8; nt++) {
            int col = warp_n * 64 + nt * 8 + tig * 2;
            float* cc = c[mt][nt];
            size_t base = (size_t)(m0 + r) * EMBED + col;
            *(float2*)(outp + base) = make_float2(cc[0], cc[1]);
            *(float2*)(outp + base + 8 * EMBED) = make_float2(cc[2], cc[3]);
        }
    }
}

// ===================== L6: combine + al2 ====================================
__global__ void combine_kernel(const float* __restrict__ as2,
                               const float* __restrict__ ad2, int n) {
    int t = threadIdx.x;
    int row = blockIdx.x * 2 + (t >> 7);
    int col = t & 127;
    if (row >= n) return;
    size_t idx = (size_t)row * EMBED + col;
    float s = 0.f;
    #pragma unroll
    for (int k = 0; k < KSPLIT; k++)
        s += g_h2p[idx + (size_t)k * MPAD * EMBED];
    g_h2[idx] = __float2half(s);
    float a = s * __ldg(&as2[col]);
    float d = s * __ldg(&ad2[col]);
    #pragma unroll
    for (int o = 16; o > 0; o >>= 1) {
        a += __shfl_down_sync(0xffffffffu, a, o);
        d += __shfl_down_sync(0xffffffffu, d, o);
    }
    __shared__ float wa[8], wd[8];
    int w = t >> 5;
    if ((t & 31) == 0) { wa[w] = a; wd[w] = d; }
    __syncthreads();
    if ((t & 127) == 0) {
        int wb = (t >> 7) * 4;
        g_als2[row] = wa[wb] + wa[wb + 1] + wa[wb + 2] + wa[wb + 3];
        g_ald2[row] = wd[wb] + wd[wb + 1] + wd[wb + 2] + wd[wb + 3];
    }
}

// ===================== L7: agg2 + classifier, single-gather flash ===========
__global__ __launch_bounds__(128) void agg2cls_kernel(const float* __restrict__ b2,
                                                      const float* __restrict__ Wc,
                                                      const float* __restrict__ bc,
                                                      float* __restrict__ out) {
    int nno = blockIdx.x;
    int t = threadIdx.x;               // 128 = channel
    int beg = g_rowptr[nno];
    int deg = g_rowptr[nno + 1] - beg;
    float ad = g_ald2[nno];

    __shared__ int   s_src[ETILE];
    __shared__ float s_w[ETILE];
    __shared__ float sred[4];

    float run_m = M_SENT, run_s = 0.f, acc = 0.f;   // replicated per thread

    for (int e0 = 0; e0 < deg; e0 += ETILE) {
        int ne = min(ETILE, deg - e0);
        float lg = M_SENT;
        if (t < ne) {
            int src = __ldg(&g_col[beg + e0 + t]);
            s_src[t] = src;
            lg = __ldg(&g_als2[src]) + ad;
            lg = lg > 0.f ? lg : NEG_SLOPE * lg;
        }
        // tile max (from registers)
        float tm = lg;
        #pragma unroll
        for (int o = 16; o > 0; o >>= 1)
            tm = fmaxf(tm, __shfl_xor_sync(0xffffffffu, tm, o));
        if ((t & 31) == 0) sred[t >> 5] = tm;
        __syncthreads();
        tm = fmaxf(fmaxf(sred[0], sred[1]), fmaxf(sred[2], sred[3]));
        float nm = fmaxf(run_m, tm);
        float sc = __expf(run_m - nm);
        run_m = nm;
        run_s *= sc;
        acc *= sc;
        // one exp per edge
        float w = (t < ne) ? __expf(lg - run_m) : 0.f;
        if (t < ne) s_w[t] = w;
        #pragma unroll
        for (int o = 16; o > 0; o >>= 1)
            w += __shfl_xor_sync(0xffffffffu, w, o);
        __syncthreads();               // sred reuse barrier
        if ((t & 31) == 0) sred[t >> 5] = w;
        __syncthreads();
        run_s += sred[0] + sred[1] + sred[2] + sred[3];
        for (int e = 0; e < ne; e++)
            acc += s_w[e] * __half2float(__ldg(&g_h2[(size_t)s_src[e] * EMBED + t]));
        __syncthreads();
    }
    float val = acc / (run_s + 1e-16f) + b2[t];
    float part = val * __ldg(&Wc[t]);
    #pragma unroll
    for (int o = 16; o > 0; o >>= 1) part += __shfl_down_sync(0xffffffffu, part, o);
    __shared__ float ws[4];
    if ((t & 31) == 0) ws[t >> 5] = part;
    __syncthreads();
    if (t == 0) out[nno] = ws[0] + ws[1] + ws[2] + ws[3] + bc[0];
}

// ===================== launch ===============================================
extern "C" void kernel_launch(void* const* d_in, const int* in_sizes, int n_in,
                              void* d_out, int out_size) {
    const float* x   = (const float*)d_in[0];
    const void*  ei  = d_in[1];
    const float* W1  = (const float*)d_in[2];
    const float* as1 = (const float*)d_in[3];
    const float* ad1 = (const float*)d_in[4];
    const float* b1  = (const float*)d_in[5];
    const float* W2  = (const float*)d_in[6];
    const float* as2 = (const float*)d_in[7];
    const float* ad2 = (const float*)d_in[8];
    const float* b2  = (const float*)d_in[9];
    const float* Wc  = (const float*)d_in[10];
    const float* bc  = (const float*)d_in[11];
    float* out = (float*)d_out;

    int E = in_sizes[1] / 2;
    int n = in_sizes[0] / EMBED;
    int mtiles = (n + MT - 1) / MT;

    cudaFuncSetAttribute(expand1_kernel, cudaFuncAttributeMaxDynamicSharedMemorySize, G1_SMEM);
    cudaFuncSetAttribute(gemm2_kernel, cudaFuncAttributeMaxDynamicSharedMemorySize, G2_SMEM);

    int decode_blocks = (2 * E + 255) / 256;
    prep_decode_kernel<<<NB_PRE + decode_blocks, 256>>>(W1, W2, as1, ad1, ei, E); // 0
    scan_logits_kernel<<<1 + (n + 31) / 32, 1024>>>(x, n);                        // 1
    fill_kernel<<<(E + n + 255) / 256, 256>>>(E, n);                              // 2
    agg1_kernel<<<n, 128>>>(x);                                                   // 3 <- profiled
    expand1_kernel<<<dim3(HEADS, mtiles), 256, G1_SMEM>>>(b1);                    // 4
    gemm2_kernel<<<dim3(mtiles, KSPLIT), 256, G2_SMEM>>>();                       // 5
    combine_kernel<<<(n + 1) / 2, 256>>>(as2, ad2, n);                            // 6
    agg2cls_kernel<<<n, 128>>>(b2, Wc, bc, out);                                  // 7
}

// round 13
// speedup vs baseline: 2.9633x; 1.4062x over previous
#include <cuda_runtime.h>
#include <cuda_bf16.h>
#include <cuda_fp16.h>
#include <cstdint>

#define N_NODES 10000
#define EDGES   160000
#define EMBED   128
#define HEADS   16
#define HC      2048
#define NEG_SLOPE 0.2f
#define M_SENT  (-1e30f)
#define MT      128
#define MPAD    (79 * 128)
#define ETILE   64

// ===================== device scratch =======================================
__device__ int   g_src[EDGES];
__device__ int   g_dst[EDGES];
__device__ int   g_deg[N_NODES];          // zero-init; re-zeroed by fill each call
__device__ int   g_rowptr[N_NODES + 1];
__device__ int   g_cursor[N_NODES];
__device__ int   g_col[EDGES + N_NODES];

__device__ float g_waS[HEADS * EMBED];
__device__ float g_waD[HEADS * EMBED];
__device__ __half g_w1t[(size_t)HC * EMBED];     // [n=2048][k=128] fp16
__device__ float g_vc[HC];                       // W2 @ Wc
__device__ float g_vs[HC];                       // W2 @ a_src2
__device__ float g_vd[HC];                       // W2 @ a_dst2
__device__ float g_const2;                       // b2.Wc + bc
__device__ float g_als1[MPAD * HEADS];
__device__ float g_ald1[MPAD * HEADS];
__device__ __half g_ax[(size_t)MPAD * HC];       // aggregated x per head, fp16
__device__ float g_c2[MPAD];                     // x2 . vc  (atomic accum)
__device__ float g_als2[MPAD];                   // x2 . vs
__device__ float g_ald2[MPAD];                   // x2 . vd

// ===================== L0: prep + decode + count ============================
template <int R, int C>
__device__ void transpose_cv(const float* __restrict__ src,
                             __half* __restrict__ dst, int bx, int by) {
    __shared__ float tile[32][33];
    int tx = threadIdx.x & 31, ty0 = threadIdx.x >> 5;
    #pragma unroll
    for (int j = 0; j < 4; j++) {
        int r = by * 32 + ty0 + j * 8, c = bx * 32 + tx;
        tile[ty0 + j * 8][tx] = src[(size_t)r * C + c];
    }
    __syncthreads();
    #pragma unroll
    for (int j = 0; j < 4; j++) {
        int rd = bx * 32 + ty0 + j * 8;
        int cd = by * 32 + tx;
        dst[(size_t)rd * R + cd] = __float2half(tile[tx][ty0 + j * 8]);
    }
}

#define NB_WA  16
#define NB_W1  256
#define NB_V   8
#define NB_PRE (NB_WA + NB_W1 + NB_V)

__global__ void prep_decode_kernel(const float* __restrict__ W1,
                                   const float* __restrict__ W2,
                                   const float* __restrict__ as1,
                                   const float* __restrict__ ad1,
                                   const float* __restrict__ as2,
                                   const float* __restrict__ ad2,
                                   const float* __restrict__ b2,
                                   const float* __restrict__ Wc,
                                   const float* __restrict__ bc,
                                   const void* __restrict__ ei, int E) {
    int b = blockIdx.x, t = threadIdx.x;
    if (b < NB_WA) {
        __shared__ float sa[EMBED], sd[EMBED];
        int h = b;
        if (t < 128) { sa[t] = as1[h * EMBED + t]; sd[t] = ad1[h * EMBED + t]; }
        __syncthreads();
        if (t < 128) {
            float ss = 0.f, ssd = 0.f;
            const float* wrow = W1 + (size_t)t * HC + h * EMBED;
            #pragma unroll 4
            for (int c = 0; c < EMBED; c++) {
                float w = wrow[c];
                ss += w * sa[c];
                ssd += w * sd[c];
            }
            g_waS[h * EMBED + t] = ss;
            g_waD[h * EMBED + t] = ssd;
        }
        return;
    }
    b -= NB_WA;
    if (b < NB_W1) { transpose_cv<128, 2048>(W1, g_w1t, b & 63, b >> 6); return; }
    b -= NB_W1;
    if (b < NB_V) {   // v vectors: one row of W2 per thread
        int k = b * 256 + t;     // 0..2047
        const float* wrow = W2 + (size_t)k * EMBED;
        float sc = 0.f, ss = 0.f, sd = 0.f;
        #pragma unroll 4
        for (int c = 0; c < EMBED; c++) {
            float w = wrow[c];
            sc += w * __ldg(&Wc[c]);
            ss += w * __ldg(&as2[c]);
            sd += w * __ldg(&ad2[c]);
        }
        g_vc[k] = sc;
        g_vs[k] = ss;
        g_vd[k] = sd;
        if (b == 0 && t < 32) {  // const2 = b2.Wc + bc
            float s = 0.f;
            for (int c = t; c < EMBED; c += 32) s += b2[c] * Wc[c];
            #pragma unroll
            for (int o = 16; o > 0; o >>= 1) s += __shfl_down_sync(0xffffffffu, s, o);
            if (t == 0) g_const2 = s + bc[0];
        }
        return;
    }
    b -= NB_V;
    const long long* p64 = (const long long*)ei;
    long long pv = p64[t];
    int ok = (pv >= 0 && pv < N_NODES);
    int is64 = __syncthreads_and(ok);
    int i = b * 256 + t;
    if (i >= 2 * E) return;
    int vi = is64 ? (int)p64[i] : ((const int*)ei)[i];
    if (i < E) g_src[i] = vi;
    else { g_dst[i - E] = vi; atomicAdd(&g_deg[vi], 1); }
}

// ===================== L1: scan (block 0) + logits1 =========================
__global__ void scan_logits_kernel(const float* __restrict__ x, int n) {
    int t = threadIdx.x;
    if (blockIdx.x == 0) {
        __shared__ int wsum[32];
        int CH = (n + 1023) / 1024;
        int base = t * CH;
        int s = 0;
        for (int k = 0; k < CH; k++) { int idx = base + k; if (idx < n) s += g_deg[idx] + 1; }
        int lane = t & 31, wid = t >> 5;
        int v = s;
        #pragma unroll
        for (int o = 1; o < 32; o <<= 1) {
            int t2 = __shfl_up_sync(0xffffffffu, v, o);
            if (lane >= o) v += t2;
        }
        if (lane == 31) wsum[wid] = v;
        __syncthreads();
        if (wid == 0) {
            int w = wsum[lane];
            #pragma unroll
            for (int o = 1; o < 32; o <<= 1) {
                int t2 = __shfl_up_sync(0xffffffffu, w, o);
                if (lane >= o) w += t2;
            }
            wsum[lane] = w;
        }
        __syncthreads();
        int excl = v - s + (wid ? wsum[wid - 1] : 0);
        int running = excl;
        for (int k = 0; k < CH; k++) {
            int idx = base + k;
            if (idx < n) {
                g_rowptr[idx] = running;
                g_cursor[idx] = running;
                running += g_deg[idx] + 1;
            }
        }
        if (t == 0) g_rowptr[n] = wsum[31];
        return;
    }
    int node = (blockIdx.x - 1) * 32 + (t >> 5);
    if (node >= n) return;
    int lane = t & 31;
    float4 xv = ((const float4*)(x + (size_t)node * EMBED))[lane];
    #pragma unroll
    for (int h = 0; h < HEADS; h++) {
        float4 wS = ((const float4*)(g_waS + h * EMBED))[lane];
        float4 wD = ((const float4*)(g_waD + h * EMBED))[lane];
        float ss = xv.x * wS.x + xv.y * wS.y + xv.z * wS.z + xv.w * wS.w;
        float sd = xv.x * wD.x + xv.y * wD.y + xv.z * wD.z + xv.w * wD.w;
        #pragma unroll
        for (int o = 16; o > 0; o >>= 1) {
            ss += __shfl_xor_sync(0xffffffffu, ss, o);
            sd += __shfl_xor_sync(0xffffffffu, sd, o);
        }
        if (lane == 0) {
            g_als1[node * HEADS + h] = ss;
            g_ald1[node * HEADS + h] = sd;
        }
    }
}

// ===================== L2: fill (+ zero accum arrays + deg self-clean) ======
__global__ void fill_kernel(int E, int n) {
    int i = blockIdx.x * blockDim.x + threadIdx.x;
    if (i < E) {
        int d = g_dst[i];
        int pos = atomicAdd(&g_cursor[d], 1);
        g_col[pos] = g_src[i];
    } else {
        int v = i - E;
        if (v < MPAD) { g_c2[v] = 0.f; g_als2[v] = 0.f; g_ald2[v] = 0.f; }
        if (v < n) {
            int pos = atomicAdd(&g_cursor[v], 1);
            g_col[pos] = v;
            g_deg[v] = 0;
        }
    }
}

// ===================== L3 (PROFILED): agg1, single-gather flash =============
__global__ __launch_bounds__(128) void agg1_kernel(const float* __restrict__ x) {
    int nno = blockIdx.x;
    int t = threadIdx.x;               // 128; phase2: t = channel
    int beg = g_rowptr[nno];
    int deg = g_rowptr[nno + 1] - beg;
    int h = t & 15, sub = t >> 4;
    int warp = t >> 5, lane = t & 31;

    __shared__ float s_ad[16], s_run_m[16], s_run_s[16], s_scale[16], s_inv[16];
    __shared__ float s_pm[4][16], s_ps[4][16];
    __shared__ int   s_src[ETILE];
    __shared__ float sw[ETILE][16];

    if (t < 16) {
        s_ad[t] = g_ald1[nno * HEADS + t];
        s_run_m[t] = M_SENT;
        s_run_s[t] = 0.f;
    }
    float acc[16];
    #pragma unroll
    for (int i = 0; i < 16; i++) acc[i] = 0.f;
    __syncthreads();

    for (int e0 = 0; e0 < deg; e0 += ETILE) {
        int ne = min(ETILE, deg - e0);
        if (t < ne) s_src[t] = __ldg(&g_col[beg + e0 + t]);
        __syncthreads();
        for (int k = t; k < ne * 16; k += 128) {
            int e = k >> 4;
            float lg = __ldg(&g_als1[s_src[e] * HEADS + h]) + s_ad[h];
            sw[e][h] = lg > 0.f ? lg : NEG_SLOPE * lg;
        }
        __syncthreads();
        float tm = M_SENT;
        for (int e = sub; e < ne; e += 8) tm = fmaxf(tm, sw[e][h]);
        tm = fmaxf(tm, __shfl_xor_sync(0xffffffffu, tm, 16));
        if (lane < 16) s_pm[warp][h] = tm;
        __syncthreads();
        if (t < 16) {
            float mt = fmaxf(fmaxf(s_pm[0][t], s_pm[1][t]), fmaxf(s_pm[2][t], s_pm[3][t]));
            float nm = fmaxf(s_run_m[t], mt);
            float sc = __expf(s_run_m[t] - nm);
            s_scale[t] = sc;
            s_run_m[t] = nm;
            s_run_s[t] *= sc;
        }
        __syncthreads();
        float psum = 0.f;
        for (int k = t; k < ne * 16; k += 128) {
            int e = k >> 4;
            float w = __expf(sw[e][h] - s_run_m[h]);
            sw[e][h] = w;
            psum += w;
        }
        psum += __shfl_xor_sync(0xffffffffu, psum, 16);
        if (lane < 16) s_ps[warp][h] = psum;
        __syncthreads();
        if (t < 16)
            s_run_s[t] += s_ps[0][t] + s_ps[1][t] + s_ps[2][t] + s_ps[3][t];
        #pragma unroll
        for (int i = 0; i < 16; i++) acc[i] *= s_scale[i];
        #pragma unroll 2
        for (int e = 0; e < ne; e++) {
            float xv = __ldg(&x[(size_t)s_src[e] * EMBED + t]);
            float4 w0 = *(float4*)&sw[e][0];
            float4 w1 = *(float4*)&sw[e][4];
            float4 w2 = *(float4*)&sw[e][8];
            float4 w3 = *(float4*)&sw[e][12];
            acc[0]  += w0.x * xv;  acc[1]  += w0.y * xv;
            acc[2]  += w0.z * xv;  acc[3]  += w0.w * xv;
            acc[4]  += w1.x * xv;  acc[5]  += w1.y * xv;
            acc[6]  += w1.z * xv;  acc[7]  += w1.w * xv;
            acc[8]  += w2.x * xv;  acc[9]  += w2.y * xv;
            acc[10] += w2.z * xv;  acc[11] += w2.w * xv;
            acc[12] += w3.x * xv;  acc[13] += w3.y * xv;
            acc[14] += w3.z * xv;  acc[15] += w3.w * xv;
        }
        __syncthreads();
    }
    if (t < 16) s_inv[t] = 1.f / (s_run_s[t] + 1e-16f);
    __syncthreads();
    #pragma unroll
    for (int i = 0; i < 16; i++)
        g_ax[(size_t)nno * HC + i * EMBED + t] = __float2half(acc[i] * s_inv[i]);
}

// ===================== mma.sync fp16 GEMM machinery =========================
#define SKW 72
#define CHUNK_B (128 * SKW * 2)

__device__ __forceinline__ void mma16816(float* c, const uint32_t* a, const uint32_t* b) {
    asm volatile("mma.sync.aligned.m16n8k16.row.col.f32.f16.f16.f32 "
        "{%0,%1,%2,%3}, {%4,%5,%6,%7}, {%8,%9}, {%0,%1,%2,%3};"
        : "+f"(c[0]), "+f"(c[1]), "+f"(c[2]), "+f"(c[3])
        : "r"(a[0]), "r"(a[1]), "r"(a[2]), "r"(a[3]), "r"(b[0]), "r"(b[1]));
}

__device__ __forceinline__ void fetch_chunk(const __half* __restrict__ src,
                                            int ld, int row0, int k0,
                                            float4* r, int tid) {
    #pragma unroll
    for (int i = 0; i < 4; i++) {
        int c = tid + i * 256;
        int row = c >> 3;
        int kk = (c & 7) * 8;
        r[i] = *(const float4*)(src + (size_t)(row0 + row) * ld + k0 + kk);
    }
}

__device__ __forceinline__ void stash_chunk(const float4* r,
                                            __half (*S)[SKW], int tid) {
    #pragma unroll
    for (int i = 0; i < 4; i++) {
        int c = tid + i * 256;
        int row = c >> 3;
        int kk = (c & 7) * 8;
        *(float4*)&S[row][kk] = r[i];
    }
}

__device__ __forceinline__ void mma_chunk(const __half (*As)[SKW],
                                          const __half (*Bs)[SKW],
                                          float c[2][8][4],
                                          int warp_m, int warp_n, int lane) {
    int g = lane >> 2, tig = lane & 3;
    #pragma unroll
    for (int ks = 0; ks < 4; ks++) {
        int k0 = ks * 16;
        uint32_t a[2][4], b[8][2];
        #pragma unroll
        for (int mt = 0; mt < 2; mt++) {
            int r = warp_m * 32 + mt * 16 + g;
            a[mt][0] = *(const uint32_t*)&As[r][k0 + tig * 2];
            a[mt][1] = *(const uint32_t*)&As[r + 8][k0 + tig * 2];
            a[mt][2] = *(const uint32_t*)&As[r][k0 + tig * 2 + 8];
            a[mt][3] = *(const uint32_t*)&As[r + 8][k0 + tig * 2 + 8];
        }
        #pragma unroll
        for (int nt = 0; nt < 8; nt++) {
            int n = warp_n * 64 + nt * 8 + g;
            b[nt][0] = *(const uint32_t*)&Bs[n][k0 + tig * 2];
            b[nt][1] = *(const uint32_t*)&Bs[n][k0 + tig * 2 + 8];
        }
        #pragma unroll
        for (int mt = 0; mt < 2; mt++)
            #pragma unroll
            for (int nt = 0; nt < 8; nt++)
                mma16816(c[mt][nt], a[mt], b[nt]);
    }
}

// ===================== L4: expand1 = ELU(aggx @ W1_h + b1) + fused dots =====
#define G1_SMEM (4 * CHUNK_B + 4 * 128 * 4)

__global__ __launch_bounds__(256) void expand1_kernel(const float* __restrict__ b1) {
    extern __shared__ char dsm[];
    __half (*Ab[2])[SKW] = {(__half(*)[SKW])dsm, (__half(*)[SKW])(dsm + 2 * CHUNK_B)};
    __half (*Bb[2])[SKW] = {(__half(*)[SKW])(dsm + CHUNK_B),
                            (__half(*)[SKW])(dsm + 3 * CHUNK_B)};
    float* s_b  = (float*)(dsm + 4 * CHUNK_B);
    float* s_vc = s_b + 128;
    float* s_vs = s_vc + 128;
    float* s_vd = s_vs + 128;

    int tid = threadIdx.x;
    int wid = tid >> 5, lane = tid & 31;
    int warp_m = wid & 3, warp_n = wid >> 2;
    int g = lane >> 2, tig = lane & 3;
    int h = blockIdx.x;
    int m0 = blockIdx.y * MT;

    if (tid < 128) {
        s_b[tid]  = b1[h * EMBED + tid];
        s_vc[tid] = g_vc[h * EMBED + tid];
        s_vs[tid] = g_vs[h * EMBED + tid];
        s_vd[tid] = g_vd[h * EMBED + tid];
    }

    float c[2][8][4];
    #pragma unroll
    for (int mt = 0; mt < 2; mt++)
        #pragma unroll
        for (int nt = 0; nt < 8; nt++)
            #pragma unroll
            for (int i = 0; i < 4; i++) c[mt][nt][i] = 0.f;

    float4 pa[4], pb[4];
    fetch_chunk(g_ax, HC, m0, h * EMBED, pa, tid);
    fetch_chunk(g_w1t, EMBED, h * 128, 0, pb, tid);
    #pragma unroll
    for (int it = 0; it < 2; it++) {
        stash_chunk(pa, Ab[it & 1], tid);
        stash_chunk(pb, Bb[it & 1], tid);
        __syncthreads();
        if (it == 0) {
            fetch_chunk(g_ax, HC, m0, h * EMBED + 64, pa, tid);
            fetch_chunk(g_w1t, EMBED, h * 128, 64, pb, tid);
        }
        mma_chunk(Ab[it & 1], Bb[it & 1], c, warp_m, warp_n, lane);
        __syncthreads();
    }

    // epilogue: bias + ELU + dot partials against v-slices (no x2 store)
    float pc[4] = {0.f, 0.f, 0.f, 0.f};
    float ps[4] = {0.f, 0.f, 0.f, 0.f};
    float pd[4] = {0.f, 0.f, 0.f, 0.f};
    #pragma unroll
    for (int mt = 0; mt < 2; mt++) {
        #pragma unroll
        for (int nt = 0; nt < 8; nt++) {
            int col = warp_n * 64 + nt * 8 + tig * 2;
            float* cc = c[mt][nt];
            #pragma unroll
            for (int q = 0; q < 2; q++) {
                float v0 = cc[q * 2 + 0] + s_b[col];
                float v1 = cc[q * 2 + 1] + s_b[col + 1];
                v0 = v0 > 0.f ? v0 : (__expf(v0) - 1.f);
                v1 = v1 > 0.f ? v1 : (__expf(v1) - 1.f);
                int slot = mt * 2 + q;
                pc[slot] += v0 * s_vc[col] + v1 * s_vc[col + 1];
                ps[slot] += v0 * s_vs[col] + v1 * s_vs[col + 1];
                pd[slot] += v0 * s_vd[col] + v1 * s_vd[col + 1];
            }
        }
    }
    #pragma unroll
    for (int o = 1; o <= 2; o <<= 1) {
        #pragma unroll
        for (int s = 0; s < 4; s++) {
            pc[s] += __shfl_xor_sync(0xffffffffu, pc[s], o);
            ps[s] += __shfl_xor_sync(0xffffffffu, ps[s], o);
            pd[s] += __shfl_xor_sync(0xffffffffu, pd[s], o);
        }
    }
    if (tig == 0) {
        #pragma unroll
        for (int mt = 0; mt < 2; mt++)
            #pragma unroll
            for (int q = 0; q < 2; q++) {
                int row = m0 + warp_m * 32 + mt * 16 + q * 8 + g;
                int slot = mt * 2 + q;
                atomicAdd(&g_c2[row], pc[slot]);
                atomicAdd(&g_als2[row], ps[slot]);
                atomicAdd(&g_ald2[row], pd[slot]);
            }
    }
}

// ===================== L5: agg2 scalar softmax + classifier =================
__global__ void agg2_kernel(float* __restrict__ out, int n) {
    int node = blockIdx.x * 8 + (threadIdx.x >> 5);
    if (node >= n) return;
    int lane = threadIdx.x & 31;
    int beg = g_rowptr[node];
    int deg = g_rowptr[node + 1] - beg;
    float ad = g_ald2[node];

    float m = M_SENT, s = 0.f, acc = 0.f;
    for (int j = lane; j < deg; j += 32) {
        int src = __ldg(&g_col[beg + j]);
        float lg = __ldg(&g_als2[src]) + ad;
        lg = lg > 0.f ? lg : NEG_SLOPE * lg;
        float c2 = __ldg(&g_c2[src]);
        if (lg > m) {
            float sc = __expf(m - lg);
            s = s * sc + 1.f;
            acc = acc * sc + c2;
            m = lg;
        } else {
            float p = __expf(lg - m);
            s += p;
            acc += p * c2;
        }
    }
    #pragma unroll
    for (int o = 16; o > 0; o >>= 1) {
        float om = __shfl_xor_sync(0xffffffffu, m, o);
        float os = __shfl_xor_sync(0xffffffffu, s, o);
        float oa = __shfl_xor_sync(0xffffffffu, acc, o);
        float nm = fmaxf(m, om);
        float e1 = __expf(m - nm), e2 = __expf(om - nm);
        s = s * e1 + os * e2;
        acc = acc * e1 + oa * e2;
        m = nm;
    }
    if (lane == 0) out[node] = acc / (s + 1e-16f) + g_const2;
}

// ===================== launch ===============================================
extern "C" void kernel_launch(void* const* d_in, const int* in_sizes, int n_in,
                              void* d_out, int out_size) {
    const float* x   = (const float*)d_in[0];
    const void*  ei  = d_in[1];
    const float* W1  = (const float*)d_in[2];
    const float* as1 = (const float*)d_in[3];
    const float* ad1 = (const float*)d_in[4];
    const float* b1  = (const float*)d_in[5];
    const float* W2  = (const float*)d_in[6];
    const float* as2 = (const float*)d_in[7];
    const float* ad2 = (const float*)d_in[8];
    const float* b2  = (const float*)d_in[9];
    const float* Wc  = (const float*)d_in[10];
    const float* bc  = (const float*)d_in[11];
    float* out = (float*)d_out;

    int E = in_sizes[1] / 2;
    int n = in_sizes[0] / EMBED;
    int mtiles = (n + MT - 1) / MT;

    cudaFuncSetAttribute(expand1_kernel, cudaFuncAttributeMaxDynamicSharedMemorySize, G1_SMEM);

    int decode_blocks = (2 * E + 255) / 256;
    prep_decode_kernel<<<NB_PRE + decode_blocks, 256>>>(W1, W2, as1, ad1, as2, ad2,
                                                        b2, Wc, bc, ei, E);       // 0
    scan_logits_kernel<<<1 + (n + 31) / 32, 1024>>>(x, n);                        // 1
    fill_kernel<<<(E + MPAD + 255) / 256, 256>>>(E, n);                           // 2
    agg1_kernel<<<n, 128>>>(x);                                                   // 3 <- profiled
    expand1_kernel<<<dim3(HEADS, mtiles), 256, G1_SMEM>>>(b1);                    // 4
    agg2_kernel<<<(n + 7) / 8, 256>>>(out, n);                                    // 5
}